// round 6
// baseline (speedup 1.0000x reference)
#include <cuda_runtime.h>
#include <cuda_bf16.h>
#include <math.h>
#include <stdint.h>

#define BATCH 64
#define IMG 224
#define HW  (IMG*IMG)          // 50176

__device__ float g_h0[64LL*64*112*112];
__device__ float g_h1[128LL*64*56*56];
__device__ float g_h2[256LL*64*28*28];
__device__ float g_h3[512LL*64*14*14];
__device__ float g_hd1[32LL*64*112*112];
__device__ float g_hd2[64LL*64*56*56];
__device__ float g_hf1[32LL*64*112*112];
__device__ float g_hf2[64LL*64*56*56];
__device__ float g_dctimg[BATCH*64];
__device__ float g_dctres[BATCH*HW];
__device__ float g_wd1s[32*9];
__device__ float g_Wre[HW];
__device__ float g_Wim[HW];
__device__ float g_D8[64];
__device__ float g_Zre[43008LL*128];
__device__ float g_Zim[43008LL*128];
__device__ float g_Ztre[24576LL*224];
__device__ float g_Ztim[24576LL*224];
__device__ float g_Gre[24576LL*224];
__device__ float g_Gim[24576LL*224];
__device__ float g_fftin[6LL*BATCH*HW];
__device__ float g_pooled[BATCH*6272];
__device__ float g_comb[BATCH*1024];
__device__ float g_buf1[BATCH*1024];
__device__ float g_fused[BATCH*512];

// ---- packed f32x2 helpers (for the fp32 GEMMs) ------------------------------
__device__ __forceinline__ unsigned long long ffma2(
    unsigned long long a, unsigned long long b, unsigned long long c)
{
    unsigned long long d;
    asm("fma.rn.f32x2 %0, %1, %2, %3;" : "=l"(d) : "l"(a), "l"(b), "l"(c));
    return d;
}
__device__ __forceinline__ unsigned long long dup2(float v) {
    unsigned long long r;
    asm("mov.b64 %0, {%1, %1};" : "=l"(r) : "f"(v));
    return r;
}
__device__ __forceinline__ float2 unpk2(unsigned long long v) {
    float2 f;
    asm("mov.b64 {%0, %1}, %2;" : "=f"(f.x), "=f"(f.y) : "l"(v));
    return f;
}

// ---- tf32 mma helpers --------------------------------------------------------
__device__ __forceinline__ uint32_t f2tf(float f) {
    uint32_t r;
    asm("cvt.rna.tf32.f32 %0, %1;" : "=r"(r) : "f"(f));
    return r;
}
__device__ __forceinline__ void mma_tf32(float* c,
    uint32_t a0, uint32_t a1, uint32_t a2, uint32_t a3, uint32_t b0, uint32_t b1)
{
    asm("mma.sync.aligned.m16n8k8.row.col.f32.tf32.tf32.f32 "
        "{%0,%1,%2,%3}, {%4,%5,%6,%7}, {%8,%9}, {%0,%1,%2,%3};"
        : "+f"(c[0]), "+f"(c[1]), "+f"(c[2]), "+f"(c[3])
        : "r"(a0), "r"(a1), "r"(a2), "r"(a3), "r"(b0), "r"(b1));
}

// ---------------------------------------------------------------------------
// TF32 tensor-core conv, parity-split smem staging.
// KH,KW taps; P = OW + KW/2 + 2; NC channels staged per sync;
// NSTEP = ceil(NC*KH*KW/8) k-steps of 8; WM m-warps (TM = WM*16 channels),
// 2 n-warps (128 outputs). Threads = WM*64.
// Output: dst[co][b][oh][ow]. Grid: (ceil(OH*OW/128), Co/TM, BATCH).
// ---------------------------------------------------------------------------
template<int KH, int KW, int P, int NC, int NSTEP, int WM>
__global__ void __launch_bounds__(WM*64) mconv_k(
    const float* __restrict__ src, const float* __restrict__ Wt,
    const float* __restrict__ bias, float* __restrict__ dst,
    int Ci, int H, int W, int OHOW, int padh, int padw,
    long long sC, long long sB)
{
    constexpr int NT = WM * 64;
    constexpr int TM = WM * 16;
    constexpr int TMP = TM + 8;            // bank-conflict-free A stride
    constexpr int OW = P - (KW / 2) - 2;
    constexpr int NR = 126 / OW + 2;
    constexpr int R  = 2 * (NR - 1) + KH;
    constexpr int KK = KH * KW;
    constexpr int CP = 2 * R * P;          // words per staged channel
    constexpr int KT = NSTEP * 8;

    __shared__ uint32_t As[KT * TMP];
    __shared__ uint32_t Sb[CP * NC];

    int tid = threadIdx.x;
    int lane = tid & 31, warp = tid >> 5;
    int wm = warp % WM, wn = warp / WM;    // wn in {0,1}
    int g = lane >> 2, ctg = lane & 3;
    int row0 = blockIdx.y * TM;
    int bz = blockIdx.z;
    int s0 = blockIdx.x * 128;
    int oh_lo = s0 / OW;
    int base_ih = 2 * oh_lo - padh;
    const float* sp = src + bz * sB;

    // per-thread B-column offsets (n = wn*64 + t*8 + g)
    int pb[8];
#pragma unroll
    for (int t = 0; t < 8; t++) {
        int s = s0 + wn * 64 + t * 8 + g;
        int sc = (s < OHOW) ? s : (OHOW - 1);
        int oh = sc / OW;
        int ow = sc - oh * OW;
        pb[t] = 2 * (oh - oh_lo) * P + ow;
    }
    // per-thread tap offsets for k = s*8+ctg and +4
    int toff0[NSTEP], toff1[NSTEP];
#pragma unroll
    for (int s = 0; s < NSTEP; s++) {
        int k = s * 8 + ctg;
#pragma unroll
        for (int h = 0; h < 2; h++) {
            int kk = k + h * 4;
            int off = 0;
            if (kk < NC * KK) {
                int cc = kk / KK;
                int tap = kk - cc * KK;
                int kh = tap / KW;
                int kw = tap - kh * KW;
                off = cc * CP + (kw & 1) * (R * P) + kh * P + (kw >> 1);
            }
            if (h == 0) toff0[s] = off; else toff1[s] = off;
        }
    }

    float acc[8][4];
#pragma unroll
    for (int t = 0; t < 8; t++)
#pragma unroll
        for (int q = 0; q < 4; q++) acc[t][q] = 0.f;

    for (int c0 = 0; c0 < Ci; c0 += NC) {
        // stage weights (tf32), zero-padded beyond NC*KK
        for (int t2 = tid; t2 < KT * TM; t2 += NT) {
            int k = t2 / TM, m = t2 - k * TM;
            uint32_t v = 0;
            if (k < NC * KK) {
                int cc = k / KK, tap = k - cc * KK;
                v = f2tf(Wt[(long long)(row0 + m) * (Ci * KK) + (c0 + cc) * KK + tap]);
            }
            As[k * TMP + m] = v;
        }
        // stage inputs (tf32), parity-split
        for (int t2 = tid; t2 < CP * NC; t2 += NT) {
            int cc = t2 / CP;
            int rem = t2 - cc * CP;
            int r = rem / (2 * P);
            int u = rem - r * 2 * P;
            int ih = base_ih + r;
            int ic = u - padw;
            float v = 0.f;
            if ((unsigned)ih < (unsigned)H && (unsigned)ic < (unsigned)W)
                v = sp[(c0 + cc) * sC + (long long)ih * W + ic];
            Sb[cc * CP + (u & 1) * (R * P) + r * P + (u >> 1)] = f2tf(v);
        }
        __syncthreads();

#pragma unroll
        for (int s = 0; s < NSTEP; s++) {
            int mb = wm * 16 + g;
            uint32_t a0 = As[(s * 8 + ctg) * TMP + mb];
            uint32_t a1 = As[(s * 8 + ctg) * TMP + mb + 8];
            uint32_t a2 = As[(s * 8 + ctg + 4) * TMP + mb];
            uint32_t a3 = As[(s * 8 + ctg + 4) * TMP + mb + 8];
            int o0 = toff0[s], o1 = toff1[s];
#pragma unroll
            for (int t = 0; t < 8; t++) {
                uint32_t b0 = Sb[o0 + pb[t]];
                uint32_t b1 = Sb[o1 + pb[t]];
                mma_tf32(acc[t], a0, a1, a2, a3, b0, b1);
            }
        }
        __syncthreads();
    }

    // epilogue: bias + relu, scatter to [co][b][s]
    long long NtotG = (long long)BATCH * OHOW;
    int r0 = row0 + wm * 16 + g;
    int r1 = r0 + 8;
    float bm0 = bias[r0], bm1 = bias[r1];
    float* d0 = dst + (long long)r0 * NtotG + (long long)bz * OHOW;
    float* d1 = dst + (long long)r1 * NtotG + (long long)bz * OHOW;
#pragma unroll
    for (int t = 0; t < 8; t++) {
        int sc = s0 + wn * 64 + t * 8 + 2 * ctg;
        if (sc < OHOW) {
            d0[sc] = fmaxf(acc[t][0] + bm0, 0.f);
            d1[sc] = fmaxf(acc[t][2] + bm1, 0.f);
        }
        if (sc + 1 < OHOW) {
            d0[sc + 1] = fmaxf(acc[t][1] + bm0, 0.f);
            d1[sc + 1] = fmaxf(acc[t][3] + bm1, 0.f);
        }
    }
}

// ---------------------------------------------------------------------------
// Dense SGEMM, FFMA2: C = alpha*A*B + beta*C + biasN (+relu)
// ---------------------------------------------------------------------------
__global__ void __launch_bounds__(256) sgemm_k(
    const float* __restrict__ A, const float* __restrict__ B, float* __restrict__ C,
    int M, int N, int K, int ldc, int ldb, float alpha, float beta,
    const float* __restrict__ biasN, int relu)
{
    __shared__ __align__(16) float As[8][128];
    __shared__ __align__(16) float Bs[8][128];
    int tid = threadIdx.x;
    int tx = tid & 15, ty = tid >> 4;
    int row0 = blockIdx.y * 128, col0 = blockIdx.x * 128;

    unsigned long long acc2[4][8];
#pragma unroll
    for (int p = 0; p < 4; p++)
#pragma unroll
        for (int j = 0; j < 8; j++) acc2[p][j] = 0ULL;

    for (int k0 = 0; k0 < K; k0 += 8) {
#pragma unroll
        for (int i = 0; i < 4; i++) {
            int idx = tid + i * 256;
            int m = idx >> 3, kk = idx & 7;
            int gm = row0 + m, gk = k0 + kk;
            float v = 0.f;
            if (gm < M && gk < K) v = A[(long long)gm * K + gk];
            As[kk][m] = v;
        }
#pragma unroll
        for (int i = 0; i < 4; i++) {
            int idx = tid + i * 256;
            int kk = idx >> 7, nn = idx & 127;
            int gn = col0 + nn, gk = k0 + kk;
            float v = 0.f;
            if (gk < K && gn < N) v = B[(long long)gk * ldb + gn];
            Bs[kk][nn] = v;
        }
        __syncthreads();
#pragma unroll
        for (int kk = 0; kk < 8; kk++) {
            unsigned long long a2[4];
#pragma unroll
            for (int p = 0; p < 4; p++)
                a2[p] = *(const unsigned long long*)&As[kk][ty * 8 + 2 * p];
            float b[8];
            *(float4*)&b[0] = *(const float4*)&Bs[kk][tx * 8];
            *(float4*)&b[4] = *(const float4*)&Bs[kk][tx * 8 + 4];
#pragma unroll
            for (int j = 0; j < 8; j++) {
                unsigned long long b2 = dup2(b[j]);
#pragma unroll
                for (int p = 0; p < 4; p++)
                    acc2[p][j] = ffma2(a2[p], b2, acc2[p][j]);
            }
        }
        __syncthreads();
    }

#pragma unroll
    for (int p = 0; p < 4; p++) {
        int gm0 = row0 + ty * 8 + 2 * p;
#pragma unroll
        for (int j = 0; j < 8; j++) {
            int gn = col0 + tx * 8 + j;
            if (gn >= N) continue;
            float2 v2 = unpk2(acc2[p][j]);
            float vv[2] = {v2.x, v2.y};
#pragma unroll
            for (int q = 0; q < 2; q++) {
                int gm = gm0 + q;
                if (gm >= M) continue;
                float v = alpha * vv[q];
                if (beta != 0.f) v += beta * C[(long long)gm * ldc + gn];
                if (biasN) v += biasN[gn];
                if (relu) v = fmaxf(v, 0.f);
                C[(long long)gm * ldc + gn] = v;
            }
        }
    }
}

// ---------------------------------------------------------------------------
// Fused complex GEMM (DFT stage 2), FFMA2.
// ---------------------------------------------------------------------------
__global__ void __launch_bounds__(256) dft2_k(
    const float* __restrict__ Are, const float* __restrict__ Aim,
    const float* __restrict__ Bre, const float* __restrict__ Bim,
    float* __restrict__ Cre, float* __restrict__ Cim)
{
    __shared__ __align__(16) float As1[8][64], As2[8][64];
    __shared__ __align__(16) float Bs1[8][128], Bs2[8][128];
    int tid = threadIdx.x;
    int tx = tid & 15, ty = tid >> 4;
    int row0 = blockIdx.y * 64, col0 = blockIdx.x * 128;

    unsigned long long are2[2][8], aim2[2][8];
#pragma unroll
    for (int p = 0; p < 2; p++)
#pragma unroll
        for (int j = 0; j < 8; j++) { are2[p][j] = 0ULL; aim2[p][j] = 0ULL; }

    for (int k0 = 0; k0 < 224; k0 += 8) {
#pragma unroll
        for (int i = 0; i < 2; i++) {
            int idx = tid + i * 256;
            int m = idx >> 3, kk = idx & 7;
            As1[kk][m] = Are[(long long)(row0 + m) * 224 + k0 + kk];
            As2[kk][m] = Aim[(long long)(row0 + m) * 224 + k0 + kk];
        }
#pragma unroll
        for (int i = 0; i < 4; i++) {
            int idx = tid + i * 256;
            int kk = idx >> 7, nn = idx & 127;
            int gn = col0 + nn;
            float v1 = 0.f, v2 = 0.f;
            if (gn < 224) {
                v1 = Bre[(k0 + kk) * 224 + gn];
                v2 = Bim[(k0 + kk) * 224 + gn];
            }
            Bs1[kk][nn] = v1;
            Bs2[kk][nn] = v2;
        }
        __syncthreads();
#pragma unroll
        for (int kk = 0; kk < 8; kk++) {
            unsigned long long a1p[2], a2p[2];
#pragma unroll
            for (int p = 0; p < 2; p++) {
                a1p[p] = *(const unsigned long long*)&As1[kk][ty * 4 + 2 * p];
                a2p[p] = *(const unsigned long long*)&As2[kk][ty * 4 + 2 * p];
            }
            float b1[8], b2[8];
            *(float4*)&b1[0] = *(const float4*)&Bs1[kk][tx * 8];
            *(float4*)&b1[4] = *(const float4*)&Bs1[kk][tx * 8 + 4];
            *(float4*)&b2[0] = *(const float4*)&Bs2[kk][tx * 8];
            *(float4*)&b2[4] = *(const float4*)&Bs2[kk][tx * 8 + 4];
#pragma unroll
            for (int j = 0; j < 8; j++) {
                unsigned long long db1 = dup2(b1[j]);
                unsigned long long db2 = dup2(b2[j]);
                unsigned long long dn2 = dup2(-b2[j]);
#pragma unroll
                for (int p = 0; p < 2; p++) {
                    are2[p][j] = ffma2(a1p[p], db1, are2[p][j]);
                    are2[p][j] = ffma2(a2p[p], dn2, are2[p][j]);
                    aim2[p][j] = ffma2(a1p[p], db2, aim2[p][j]);
                    aim2[p][j] = ffma2(a2p[p], db1, aim2[p][j]);
                }
            }
        }
        __syncthreads();
    }

#pragma unroll
    for (int p = 0; p < 2; p++) {
        long long gm0 = row0 + ty * 4 + 2 * p;
#pragma unroll
        for (int j = 0; j < 8; j++) {
            int gn = col0 + tx * 8 + j;
            if (gn < 224) {
                float2 vr = unpk2(are2[p][j]);
                float2 vi = unpk2(aim2[p][j]);
                Cre[gm0 * 224 + gn] = vr.x;
                Cre[(gm0 + 1) * 224 + gn] = vr.y;
                Cim[gm0 * 224 + gn] = vi.x;
                Cim[(gm0 + 1) * 224 + gn] = vi.y;
            }
        }
    }
}

// ---------------------------------------------------------------------------
// Small kernels
// ---------------------------------------------------------------------------
__global__ void genW_k(float* Wre, float* Wim) {
    int gid = blockIdx.x * blockDim.x + threadIdx.x;
    if (gid >= HW) return;
    int j = gid / IMG, k = gid % IMG;
    int r = (j * k) % IMG;
    float a = 2.f * (float)r / (float)IMG;
    Wre[gid] = cospif(a);
    Wim[gid] = -sinpif(a);
}

__global__ void genD8_k(float* D) {
    int tid = threadIdx.x;
    if (tid >= 64) return;
    int i = tid >> 3, j = tid & 7;
    float v = 0.5f * cospif((float)((2 * j + 1) * i) / 16.f);
    if (i == 0) v *= 0.7071067811865476f;
    D[tid] = v;
}

__global__ void wsum_k(const float* __restrict__ wd1, float* __restrict__ wd1s) {
    int tid = blockIdx.x * blockDim.x + threadIdx.x;
    if (tid >= 288) return;
    int o = tid / 9, r = tid % 9;
    wd1s[tid] = wd1[(o * 3 + 0) * 9 + r] + wd1[(o * 3 + 1) * 9 + r] + wd1[(o * 3 + 2) * 9 + r];
}

__global__ void dct_mean_k(const float* __restrict__ x, const float* __restrict__ D,
                           float* __restrict__ dctimg)
{
    __shared__ float part[8][64];
    __shared__ float Mb[64];
    __shared__ float T[64];
    int b = blockIdx.x;
    int tid = threadIdx.x;
    int ij = tid & 63, ch = tid >> 6;
    int i = ij >> 3, j = ij & 7;
    const float* xb = x + (long long)b * 3 * HW;
    float s = 0.f;
    for (int blk = ch; blk < 784; blk += 8) {
        int m = blk / 28, n = blk % 28;
        int idx = (m * 8 + i) * IMG + (n * 8 + j);
        s += 0.299f * xb[idx] + 0.587f * xb[idx + HW] + 0.114f * xb[idx + 2 * HW];
    }
    part[ch][ij] = s;
    __syncthreads();
    if (tid < 64) {
        float t = 0.f;
        for (int c = 0; c < 8; c++) t += part[c][tid];
        Mb[tid] = t * (255.f / 784.f);
    }
    __syncthreads();
    if (tid < 64) {
        float t = 0.f;
        for (int k = 0; k < 8; k++) t += D[i * 8 + k] * Mb[k * 8 + j];
        T[tid] = t;
    }
    __syncthreads();
    if (tid < 64) {
        float o = 0.f;
        for (int k = 0; k < 8; k++) o += T[i * 8 + k] * D[j * 8 + k];
        dctimg[b * 64 + tid] = o;
    }
}

__global__ void resize_k(const float* __restrict__ dctimg, float* __restrict__ out) {
    int gid = blockIdx.x * blockDim.x + threadIdx.x;
    if (gid >= BATCH * HW) return;
    int ow = gid % IMG;
    int t = gid / IMG;
    int oh = t % IMG;
    int b = t / IMG;
    float fh = (oh + 0.5f) * (8.f / 224.f) - 0.5f;
    float fw = (ow + 0.5f) * (8.f / 224.f) - 0.5f;
    fh = fminf(fmaxf(fh, 0.f), 7.f);
    fw = fminf(fmaxf(fw, 0.f), 7.f);
    int h0 = (int)floorf(fh), w0 = (int)floorf(fw);
    int h1 = min(h0 + 1, 7), w1 = min(w0 + 1, 7);
    float ah = fh - (float)h0, aw = fw - (float)w0;
    const float* d = dctimg + b * 64;
    float v00 = d[h0 * 8 + w0], v01 = d[h0 * 8 + w1];
    float v10 = d[h1 * 8 + w0], v11 = d[h1 * 8 + w1];
    out[gid] = (1.f - ah) * ((1.f - aw) * v00 + aw * v01) + ah * ((1.f - aw) * v10 + aw * v11);
}

__global__ void transpose_z_k(const float* __restrict__ src, float* __restrict__ dst) {
    __shared__ float tile[32][33];
    int m = blockIdx.z;
    int i0 = blockIdx.x * 32;
    int k0 = blockIdx.y * 32;
    int tx = threadIdx.x, ty = threadIdx.y;
    tile[ty][tx] = src[((long long)m * 224 + i0 + ty) * 128 + k0 + tx];
    __syncthreads();
    dst[((long long)m * 128 + k0 + ty) * 224 + i0 + tx] = tile[tx][ty];
}

__global__ void fftin2_k(const float* __restrict__ Gc, float* __restrict__ fftin,
                         int p, float sgn) {
    __shared__ float tile[32][33];
    int m = blockIdx.z;
    int b = m / 3, c = m % 3;
    int i0 = blockIdx.y * 32;
    int j0 = blockIdx.x * 32;
    int tx = threadIdx.x, ty = threadIdx.y;
    int w = i0 + ty, h = j0 + tx;
    float v;
    if (w < 113) {
        v = Gc[((long long)m * 128 + w) * 224 + h];
    } else {
        int hs = (224 - h) % 224;
        v = sgn * Gc[((long long)m * 128 + (224 - w)) * 224 + hs];
    }
    tile[ty][tx] = v;
    __syncthreads();
    fftin[((long long)(2 * c + p) * BATCH + b) * HW + (j0 + ty) * 224 + (i0 + tx)] = tile[tx][ty];
}

__global__ void pool7_k(const float* __restrict__ src, float* __restrict__ pooled, int base) {
    int gid = blockIdx.x * blockDim.x + threadIdx.x;
    if (gid >= 64 * BATCH * 49) return;
    int j = gid % 7;
    int t = gid / 7;
    int i = t % 7;
    t /= 7;
    int c = t % 64;
    int b = t / 64;
    const float* s = src + ((long long)c * BATCH + b) * 56 * 56;
    float acc = 0.f;
#pragma unroll
    for (int p = 0; p < 8; p++)
#pragma unroll
        for (int q = 0; q < 8; q++)
            acc += s[(i * 8 + p) * 56 + (j * 8 + q)];
    pooled[b * 6272 + base + c * 49 + i * 7 + j] = acc * (1.f / 64.f);
}

__global__ void gap_k(const float* __restrict__ h3, float* __restrict__ comb) {
    int gid = blockIdx.x * blockDim.x + threadIdx.x;
    if (gid >= 512 * BATCH) return;
    int c = gid / BATCH, b = gid % BATCH;
    const float* s = h3 + ((long long)c * BATCH + b) * 196;
    float acc = 0.f;
    for (int t = 0; t < 196; t++) acc += s[t];
    comb[b * 1024 + c] = acc * (1.f / 196.f);
}

__global__ void cls_k(const float* __restrict__ fused, const float* __restrict__ Wc,
                      const float* __restrict__ bc, const float* __restrict__ temp,
                      float* __restrict__ out)
{
    int tid = threadIdx.x;
    if (tid >= 128) return;
    int b = tid >> 1, j = tid & 1;
    float s = bc[j];
    const float* f = fused + b * 512;
    for (int k = 0; k < 512; k++) s += f[k] * Wc[k * 2 + j];
    out[b * 2 + j] = s;
    out[128 + b * 2 + j] = s / temp[0];
}

// ---------------------------------------------------------------------------
static void run_sgemm(const float* A, const float* B, float* C, int M, int N, int K,
                      const float* biasN, int relu,
                      float alpha = 1.f, float beta = 0.f, int ldc = -1, int ldb = -1)
{
    if (ldc < 0) ldc = N;
    if (ldb < 0) ldb = N;
    dim3 grid((N + 127) / 128, (M + 127) / 128);
    sgemm_k<<<grid, 256>>>(A, B, C, M, N, K, ldc, ldb, alpha, beta, biasN, relu);
}

extern "C" void kernel_launch(void* const* d_in, const int* in_sizes, int n_in,
                              void* d_out, int out_size)
{
    const float* x      = (const float*)d_in[0];
    const float* w_stem = (const float*)d_in[1];
    const float* b_stem = (const float*)d_in[2];
    const float* w1     = (const float*)d_in[3];
    const float* b1     = (const float*)d_in[4];
    const float* w2     = (const float*)d_in[5];
    const float* b2     = (const float*)d_in[6];
    const float* w3     = (const float*)d_in[7];
    const float* b3     = (const float*)d_in[8];
    const float* wd1    = (const float*)d_in[9];
    const float* bd1    = (const float*)d_in[10];
    const float* wd2    = (const float*)d_in[11];
    const float* bd2    = (const float*)d_in[12];
    const float* wf1    = (const float*)d_in[13];
    const float* bf1    = (const float*)d_in[14];
    const float* wf2    = (const float*)d_in[15];
    const float* bf2    = (const float*)d_in[16];
    const float* W_freq = (const float*)d_in[17];
    const float* b_freq = (const float*)d_in[18];
    const float* W_fu1  = (const float*)d_in[19];
    const float* b_fu1  = (const float*)d_in[20];
    const float* W_fu2  = (const float*)d_in[21];
    const float* b_fu2  = (const float*)d_in[22];
    const float* W_cls  = (const float*)d_in[23];
    const float* b_cls  = (const float*)d_in[24];
    const float* temp   = (const float*)d_in[25];
    float* out = (float*)d_out;

    float *h0, *h1, *h2, *h3, *hd1, *hd2, *hf1, *hf2;
    float *dctimg, *dctres, *wd1s, *Wre, *Wim, *D8;
    float *Zre, *Zim, *Ztre, *Ztim, *Gre, *Gim, *fftin;
    float *pooled, *comb, *buf1, *fused;
    cudaGetSymbolAddress((void**)&h0, g_h0);
    cudaGetSymbolAddress((void**)&h1, g_h1);
    cudaGetSymbolAddress((void**)&h2, g_h2);
    cudaGetSymbolAddress((void**)&h3, g_h3);
    cudaGetSymbolAddress((void**)&hd1, g_hd1);
    cudaGetSymbolAddress((void**)&hd2, g_hd2);
    cudaGetSymbolAddress((void**)&hf1, g_hf1);
    cudaGetSymbolAddress((void**)&hf2, g_hf2);
    cudaGetSymbolAddress((void**)&dctimg, g_dctimg);
    cudaGetSymbolAddress((void**)&dctres, g_dctres);
    cudaGetSymbolAddress((void**)&wd1s, g_wd1s);
    cudaGetSymbolAddress((void**)&Wre, g_Wre);
    cudaGetSymbolAddress((void**)&Wim, g_Wim);
    cudaGetSymbolAddress((void**)&D8, g_D8);
    cudaGetSymbolAddress((void**)&Zre, g_Zre);
    cudaGetSymbolAddress((void**)&Zim, g_Zim);
    cudaGetSymbolAddress((void**)&Ztre, g_Ztre);
    cudaGetSymbolAddress((void**)&Ztim, g_Ztim);
    cudaGetSymbolAddress((void**)&Gre, g_Gre);
    cudaGetSymbolAddress((void**)&Gim, g_Gim);
    cudaGetSymbolAddress((void**)&fftin, g_fftin);
    cudaGetSymbolAddress((void**)&pooled, g_pooled);
    cudaGetSymbolAddress((void**)&comb, g_comb);
    cudaGetSymbolAddress((void**)&buf1, g_buf1);
    cudaGetSymbolAddress((void**)&fused, g_fused);

    // ---- init constants ----
    genW_k<<<(HW + 255) / 256, 256>>>(Wre, Wim);
    genD8_k<<<1, 64>>>(D8);
    wsum_k<<<2, 256>>>(wd1, wd1s);

    // ---- CNN backbone (tf32 tensor-core convs) ----
    // stem: 3->64, 7x7 s2 pad2; NC=1, KK=49 -> NSTEP=7; TM=64 (WM=4)
    mconv_k<7,7,117,1,7,4><<<dim3(98, 1, BATCH), 256>>>(
        x, w_stem, b_stem, h0, 3, 224, 224, 12544, 2, 2, (long long)HW, 3LL * HW);
    // conv1: 64->128, 112->56; NC=4 -> K36 pad40, NSTEP=5
    mconv_k<3,3,59,4,5,4><<<dim3(25, 2, BATCH), 256>>>(
        h0, w1, b1, h1, 64, 112, 112, 3136, 0, 0, 64LL * 12544, 12544LL);
    // conv2: 128->256, 56->28
    mconv_k<3,3,31,4,5,4><<<dim3(7, 4, BATCH), 256>>>(
        h1, w2, b2, h2, 128, 56, 56, 784, 0, 0, 64LL * 3136, 3136LL);
    // conv3: 256->512, 28->14
    mconv_k<3,3,17,4,5,4><<<dim3(2, 8, BATCH), 256>>>(
        h2, w3, b3, h3, 256, 28, 28, 196, 0, 0, 64LL * 784, 784LL);
    gap_k<<<(512 * BATCH + 255) / 256, 256>>>(h3, comb);

    // ---- DCT branch ----
    dct_mean_k<<<BATCH, 512>>>(x, D8, dctimg);
    resize_k<<<(BATCH * HW + 255) / 256, 256>>>(dctimg, dctres);
    // wd1 (folded, Ci=1): 1->32; NC=1, KK=9 -> NSTEP=2; TM=32 (WM=2)
    mconv_k<3,3,115,1,2,2><<<dim3(98, 1, BATCH), 128>>>(
        dctres, wd1s, bd1, hd1, 1, 224, 224, 12544, 0, 0, 0LL, (long long)HW);
    // wd2: 32->64, 112->56; NC=4
    mconv_k<3,3,59,4,5,4><<<dim3(25, 1, BATCH), 256>>>(
        hd1, wd2, bd2, hd2, 32, 112, 112, 3136, 0, 0, 64LL * 12544, 12544LL);
    pool7_k<<<(64 * BATCH * 49 + 255) / 256, 256>>>(hd2, pooled, 0);

    // ---- FFT branch (Hermitian-reduced DFT, fp32) ----
    run_sgemm(x, Wre, Zre, 43008, 128, 224, nullptr, 0, 1.f, 0.f, 128, 224);
    run_sgemm(x, Wim, Zim, 43008, 128, 224, nullptr, 0, 1.f, 0.f, 128, 224);
    {
        dim3 tgrid(7, 4, 192), tblk(32, 32);
        transpose_z_k<<<tgrid, tblk>>>(Zre, Ztre);
        transpose_z_k<<<tgrid, tblk>>>(Zim, Ztim);
    }
    dft2_k<<<dim3(2, 384), 256>>>(Ztre, Ztim, Wre, Wim, Gre, Gim);
    {
        dim3 tgrid(7, 7, 192), tblk(32, 32);
        fftin2_k<<<tgrid, tblk>>>(Gre, fftin, 0,  1.f);
        fftin2_k<<<tgrid, tblk>>>(Gim, fftin, 1, -1.f);
    }
    // wf1: 6->32; NC=6, K54 pad56, NSTEP=7; TM=32
    mconv_k<3,3,115,6,7,2><<<dim3(98, 1, BATCH), 128>>>(
        fftin, wf1, bf1, hf1, 6, 224, 224, 12544, 0, 0, (long long)BATCH * HW, (long long)HW);
    // wf2: 32->64
    mconv_k<3,3,59,4,5,4><<<dim3(25, 1, BATCH), 256>>>(
        hf1, wf2, bf2, hf2, 32, 112, 112, 3136, 0, 0, 64LL * 12544, 12544LL);
    pool7_k<<<(64 * BATCH * 49 + 255) / 256, 256>>>(hf2, pooled, 3136);

    // ---- fusion + classifier (fp32) ----
    run_sgemm(pooled, W_freq, comb + 512, 64, 512, 6272, b_freq, 1, 1.f, 0.f, 1024);
    run_sgemm(comb, W_fu1, buf1, 64, 1024, 1024, b_fu1, 1);
    run_sgemm(buf1, W_fu2, fused, 64, 512, 1024, b_fu2, 1);
    cls_k<<<1, 128>>>(fused, W_cls, b_cls, temp, out);
}

// round 7
// speedup vs baseline: 1.9417x; 1.9417x over previous
#include <cuda_runtime.h>
#include <cuda_bf16.h>
#include <math.h>
#include <stdint.h>

#define BATCH 64
#define IMG 224
#define HW  (IMG*IMG)          // 50176

__device__ float g_h0[64LL*64*112*112];
__device__ float g_h1[128LL*64*56*56];
__device__ float g_h2[256LL*64*28*28];
__device__ float g_h3[512LL*64*14*14];
__device__ float g_hd1[32LL*64*112*112];
__device__ float g_hd2[64LL*64*56*56];
__device__ float g_hf1[32LL*64*112*112];
__device__ float g_hf2[64LL*64*56*56];
__device__ float g_dctimg[BATCH*64];
__device__ float g_dctres[BATCH*HW];
__device__ float g_wd1s[32*9];
__device__ float g_Wre[HW];
__device__ float g_Wim[HW];
__device__ float g_D8[64];
__device__ float g_Zre[43008LL*128];     // [192][224 i][128 kf]
__device__ float g_Zim[43008LL*128];
__device__ float g_Gre[24576LL*224];     // [192][128 kf][224 h]
__device__ float g_Gim[24576LL*224];
__device__ float g_fftin[6LL*BATCH*HW];
__device__ float g_pooled[BATCH*6272];
__device__ float g_comb[BATCH*1024];
__device__ float g_buf1[BATCH*1024];
__device__ float g_fused[BATCH*512];

// ---- packed f32x2 helpers ---------------------------------------------------
__device__ __forceinline__ unsigned long long ffma2(
    unsigned long long a, unsigned long long b, unsigned long long c)
{
    unsigned long long d;
    asm("fma.rn.f32x2 %0, %1, %2, %3;" : "=l"(d) : "l"(a), "l"(b), "l"(c));
    return d;
}
__device__ __forceinline__ unsigned long long dup2(float v) {
    unsigned long long r;
    asm("mov.b64 %0, {%1, %1};" : "=l"(r) : "f"(v));
    return r;
}
__device__ __forceinline__ float2 unpk2(unsigned long long v) {
    float2 f;
    asm("mov.b64 {%0, %1}, %2;" : "=f"(f.x), "=f"(f.y) : "l"(v));
    return f;
}

// ---------------------------------------------------------------------------
// Direct stride-2 conv, parity-split smem staging, FFMA2 accumulation,
// cp.async double-buffered channel-group pipeline.
// KH,KW taps; P = OW + KW/2 + 2; TM = Co tile (8 rows/thread); NC channels
// per group; DB = 1 (single shot, requires Ci == NC) or 2 (ping-pong).
// Threads = 2*TM. Grid: (ceil(OH*OW/128), Co/TM, BATCH).
// ---------------------------------------------------------------------------
template<int KH, int KW, int P, int TM, int NC, int DB>
__global__ void __launch_bounds__(2*TM) dconv_k(
    const float* __restrict__ src, const float* __restrict__ Wt,
    const float* __restrict__ bias, float* __restrict__ dst,
    int Ci, int H, int W, int OHOW, int padh, int padw,
    long long sC, long long sB)
{
    constexpr int NT = 2 * TM;
    constexpr int OW = P - (KW / 2) - 2;
    constexpr int NR = 126 / OW + 2;
    constexpr int R  = 2 * (NR - 1) + KH;
    constexpr int KK = KH * KW;
    constexpr int CP = 2 * R * P;          // floats per staged channel
    constexpr int WSZ = KK * TM * NC;
    constexpr int SSZ = CP * NC;

    __shared__ __align__(16) float As[DB * WSZ];
    __shared__ __align__(16) float Sb[DB * SSZ];

    int tid = threadIdx.x;
    int tx = tid & 15, ty = tid >> 4;
    int row0 = blockIdx.y * TM;
    int bz = blockIdx.z;
    int s0 = blockIdx.x * 128;
    int oh_lo = s0 / OW;
    int base_ih = 2 * oh_lo - padh;
    const float* sp = src + bz * sB;

    uint32_t as_u = (uint32_t)__cvta_generic_to_shared(As);
    uint32_t sb_u = (uint32_t)__cvta_generic_to_shared(Sb);

    int pbase[8];
    unsigned okmask = 0;
#pragma unroll
    for (int j = 0; j < 8; j++) {
        int s = s0 + j * 16 + tx;
        if (s < OHOW) okmask |= (1u << j);
        int sc = (s < OHOW) ? s : (OHOW - 1);
        int oh = sc / OW;
        int ow = sc - oh * OW;
        pbase[j] = 2 * (oh - oh_lo) * P + ow;
    }

    unsigned long long acc2[4][8];
#pragma unroll
    for (int p = 0; p < 4; p++)
#pragma unroll
        for (int j = 0; j < 8; j++) acc2[p][j] = 0ULL;

    auto stage = [&](int c0, int pp) {
        uint32_t ab = as_u + pp * WSZ * 4;
        for (int t = tid; t < WSZ; t += NT) {
            int cc = t / (KK * TM);
            int rem = t - cc * (KK * TM);
            int m = rem / KK, tap = rem - m * KK;
            const float* g = Wt + (long long)(row0 + m) * (Ci * KK) + (c0 + cc) * KK + tap;
            uint32_t d = ab + (uint32_t)(((cc * KK + tap) * TM + m) * 4);
            asm volatile("cp.async.ca.shared.global [%0], [%1], 4;" :: "r"(d), "l"(g));
        }
        uint32_t sbb = sb_u + pp * SSZ * 4;
        for (int t = tid; t < SSZ; t += NT) {
            int cc = t / CP;
            int rem = t - cc * CP;
            int r = rem / (2 * P);
            int u = rem - r * 2 * P;
            int ih = base_ih + r;
            int ic = u - padw;
            bool ok = ((unsigned)ih < (unsigned)H) && ((unsigned)ic < (unsigned)W);
            const float* g = sp + (c0 + cc) * sC + (ok ? ((long long)ih * W + ic) : 0LL);
            uint32_t d = sbb + (uint32_t)((cc * CP + (u & 1) * (R * P) + r * P + (u >> 1)) * 4);
            int sz = ok ? 4 : 0;
            asm volatile("cp.async.ca.shared.global [%0], [%1], 4, %2;"
                         :: "r"(d), "l"(g), "r"(sz));
        }
        asm volatile("cp.async.commit_group;");
    };

    auto compute = [&](int pp) {
        const float* Ap = As + pp * WSZ;
        const float* Bp = Sb + pp * SSZ;
#pragma unroll
        for (int cc = 0; cc < NC; cc++) {
#pragma unroll
            for (int kh = 0; kh < KH; kh++) {
#pragma unroll
                for (int kw = 0; kw < KW; kw++) {
                    const float* aw = Ap + (cc * KK + kh * KW + kw) * TM + ty * 8;
                    const float* bb = Bp + cc * CP + (kw & 1) * (R * P) + kh * P + (kw >> 1);
                    unsigned long long a2[4];
#pragma unroll
                    for (int p = 0; p < 4; p++)
                        a2[p] = *(const unsigned long long*)&aw[2 * p];
#pragma unroll
                    for (int j = 0; j < 8; j++) {
                        unsigned long long b2 = dup2(bb[pbase[j]]);
#pragma unroll
                        for (int p = 0; p < 4; p++)
                            acc2[p][j] = ffma2(a2[p], b2, acc2[p][j]);
                    }
                }
            }
        }
    };

    stage(0, 0);
    int p = 0;
    for (int c0 = 0; c0 < Ci; c0 += NC) {
        if (DB == 2) {
            if (c0 + NC < Ci) {
                stage(c0 + NC, p ^ 1);
                asm volatile("cp.async.wait_group 1;");
            } else {
                asm volatile("cp.async.wait_group 0;");
            }
        } else {
            asm volatile("cp.async.wait_group 0;");
        }
        __syncthreads();
        compute(p);
        __syncthreads();
        p ^= 1;
    }

    long long NtotG = (long long)BATCH * OHOW;
#pragma unroll
    for (int q = 0; q < 4; q++) {
        int gm0 = row0 + ty * 8 + 2 * q;
        float bm0 = bias[gm0], bm1 = bias[gm0 + 1];
        float* d0 = dst + (long long)gm0 * NtotG + (long long)bz * OHOW;
        float* d1 = d0 + NtotG;
#pragma unroll
        for (int j = 0; j < 8; j++) {
            if (okmask & (1u << j)) {
                int s = s0 + j * 16 + tx;
                float2 v = unpk2(acc2[q][j]);
                d0[s] = fmaxf(v.x + bm0, 0.f);
                d1[s] = fmaxf(v.y + bm1, 0.f);
            }
        }
    }
}

// ---------------------------------------------------------------------------
// Dense SGEMM, FFMA2 (FC layers): C = alpha*A*B + beta*C + biasN (+relu)
// ---------------------------------------------------------------------------
__global__ void __launch_bounds__(256) sgemm_k(
    const float* __restrict__ A, const float* __restrict__ B, float* __restrict__ C,
    int M, int N, int K, int ldc, int ldb, float alpha, float beta,
    const float* __restrict__ biasN, int relu)
{
    __shared__ __align__(16) float As[8][128];
    __shared__ __align__(16) float Bs[8][128];
    int tid = threadIdx.x;
    int tx = tid & 15, ty = tid >> 4;
    int row0 = blockIdx.y * 128, col0 = blockIdx.x * 128;

    unsigned long long acc2[4][8];
#pragma unroll
    for (int p = 0; p < 4; p++)
#pragma unroll
        for (int j = 0; j < 8; j++) acc2[p][j] = 0ULL;

    for (int k0 = 0; k0 < K; k0 += 8) {
#pragma unroll
        for (int i = 0; i < 4; i++) {
            int idx = tid + i * 256;
            int m = idx >> 3, kk = idx & 7;
            int gm = row0 + m, gk = k0 + kk;
            float v = 0.f;
            if (gm < M && gk < K) v = A[(long long)gm * K + gk];
            As[kk][m] = v;
        }
#pragma unroll
        for (int i = 0; i < 4; i++) {
            int idx = tid + i * 256;
            int kk = idx >> 7, nn = idx & 127;
            int gn = col0 + nn, gk = k0 + kk;
            float v = 0.f;
            if (gk < K && gn < N) v = B[(long long)gk * ldb + gn];
            Bs[kk][nn] = v;
        }
        __syncthreads();
#pragma unroll
        for (int kk = 0; kk < 8; kk++) {
            unsigned long long a2[4];
#pragma unroll
            for (int p = 0; p < 4; p++)
                a2[p] = *(const unsigned long long*)&As[kk][ty * 8 + 2 * p];
            float b[8];
            *(float4*)&b[0] = *(const float4*)&Bs[kk][tx * 8];
            *(float4*)&b[4] = *(const float4*)&Bs[kk][tx * 8 + 4];
#pragma unroll
            for (int j = 0; j < 8; j++) {
                unsigned long long b2 = dup2(b[j]);
#pragma unroll
                for (int p = 0; p < 4; p++)
                    acc2[p][j] = ffma2(a2[p], b2, acc2[p][j]);
            }
        }
        __syncthreads();
    }

#pragma unroll
    for (int p = 0; p < 4; p++) {
        int gm0 = row0 + ty * 8 + 2 * p;
#pragma unroll
        for (int j = 0; j < 8; j++) {
            int gn = col0 + tx * 8 + j;
            if (gn >= N) continue;
            float2 v2 = unpk2(acc2[p][j]);
            float vv[2] = {v2.x, v2.y};
#pragma unroll
            for (int q = 0; q < 2; q++) {
                int gm = gm0 + q;
                if (gm >= M) continue;
                float v = alpha * vv[q];
                if (beta != 0.f) v += beta * C[(long long)gm * ldc + gn];
                if (biasN) v += biasN[gn];
                if (relu) v = fmaxf(v, 0.f);
                C[(long long)gm * ldc + gn] = v;
            }
        }
    }
}

// ---------------------------------------------------------------------------
// DFT stage 1 fused: Zre = X*Wre[:, :128], Zim = X*Wim[:, :128].
// X [43008, 224] (rows = (img, i)); Z layout [img][i][kf] (ld 128).
// M-tile 64, N = 128, 256 threads.
// ---------------------------------------------------------------------------
__global__ void __launch_bounds__(256) dft1_k(
    const float* __restrict__ X,
    const float* __restrict__ Bre, const float* __restrict__ Bim,
    float* __restrict__ Zre, float* __restrict__ Zim)
{
    __shared__ __align__(16) float As[8][64];
    __shared__ __align__(16) float Bs1[8][128], Bs2[8][128];
    int tid = threadIdx.x;
    int tx = tid & 15, ty = tid >> 4;
    int row0 = blockIdx.y * 64;

    unsigned long long zre[2][8], zim[2][8];
#pragma unroll
    for (int p = 0; p < 2; p++)
#pragma unroll
        for (int j = 0; j < 8; j++) { zre[p][j] = 0ULL; zim[p][j] = 0ULL; }

    for (int k0 = 0; k0 < 224; k0 += 8) {
#pragma unroll
        for (int i = 0; i < 2; i++) {
            int idx = tid + i * 256;
            int m = idx >> 3, kk = idx & 7;
            As[kk][m] = X[(long long)(row0 + m) * 224 + k0 + kk];
        }
#pragma unroll
        for (int i = 0; i < 4; i++) {
            int idx = tid + i * 256;
            int kk = idx >> 7, nn = idx & 127;
            Bs1[kk][nn] = Bre[(k0 + kk) * 224 + nn];
            Bs2[kk][nn] = Bim[(k0 + kk) * 224 + nn];
        }
        __syncthreads();
#pragma unroll
        for (int kk = 0; kk < 8; kk++) {
            unsigned long long a2[2];
#pragma unroll
            for (int p = 0; p < 2; p++)
                a2[p] = *(const unsigned long long*)&As[kk][ty * 4 + 2 * p];
            float b1[8], b2[8];
            *(float4*)&b1[0] = *(const float4*)&Bs1[kk][tx * 8];
            *(float4*)&b1[4] = *(const float4*)&Bs1[kk][tx * 8 + 4];
            *(float4*)&b2[0] = *(const float4*)&Bs2[kk][tx * 8];
            *(float4*)&b2[4] = *(const float4*)&Bs2[kk][tx * 8 + 4];
#pragma unroll
            for (int j = 0; j < 8; j++) {
                unsigned long long db1 = dup2(b1[j]);
                unsigned long long db2 = dup2(b2[j]);
#pragma unroll
                for (int p = 0; p < 2; p++) {
                    zre[p][j] = ffma2(a2[p], db1, zre[p][j]);
                    zim[p][j] = ffma2(a2[p], db2, zim[p][j]);
                }
            }
        }
        __syncthreads();
    }

#pragma unroll
    for (int p = 0; p < 2; p++) {
        long long gm0 = row0 + ty * 4 + 2 * p;
#pragma unroll
        for (int j = 0; j < 8; j++) {
            int gn = tx * 8 + j;
            float2 vr = unpk2(zre[p][j]);
            float2 vi = unpk2(zim[p][j]);
            Zre[gm0 * 128 + gn] = vr.x;
            Zre[(gm0 + 1) * 128 + gn] = vr.y;
            Zim[gm0 * 128 + gn] = vi.x;
            Zim[(gm0 + 1) * 128 + gn] = vi.y;
        }
    }
}

// ---------------------------------------------------------------------------
// DFT stage 2 fused complex GEMM reading Z in [img][i][kf] layout directly:
// G[img][kf][h] = sum_i Z[img][i][kf] * W[i][h] (complex, W = Wre - i*Wim form
// already baked: Gre = Zre*Wre - Zim*Wim; Gim = Zre*Wim + Zim*Wre).
// M = (img, kf) = 24576 rows, row0 = blockIdx.y*64 (64 | 128 so single img).
// ---------------------------------------------------------------------------
__global__ void __launch_bounds__(256) dft2_k(
    const float* __restrict__ Zre, const float* __restrict__ Zim,
    const float* __restrict__ Bre, const float* __restrict__ Bim,
    float* __restrict__ Cre, float* __restrict__ Cim)
{
    __shared__ __align__(16) float As1[8][64], As2[8][64];
    __shared__ __align__(16) float Bs1[8][128], Bs2[8][128];
    int tid = threadIdx.x;
    int tx = tid & 15, ty = tid >> 4;
    int row0 = blockIdx.y * 64, col0 = blockIdx.x * 128;
    int img = row0 >> 7;
    int kf0 = row0 & 127;

    unsigned long long are2[2][8], aim2[2][8];
#pragma unroll
    for (int p = 0; p < 2; p++)
#pragma unroll
        for (int j = 0; j < 8; j++) { are2[p][j] = 0ULL; aim2[p][j] = 0ULL; }

    for (int k0 = 0; k0 < 224; k0 += 8) {
#pragma unroll
        for (int i = 0; i < 2; i++) {
            int idx = tid + i * 256;
            int m = idx >> 3, kk = idx & 7;
            long long zoff = ((long long)img * 224 + k0 + kk) * 128 + kf0 + m;
            As1[kk][m] = Zre[zoff];
            As2[kk][m] = Zim[zoff];
        }
#pragma unroll
        for (int i = 0; i < 4; i++) {
            int idx = tid + i * 256;
            int kk = idx >> 7, nn = idx & 127;
            int gn = col0 + nn;
            float v1 = 0.f, v2 = 0.f;
            if (gn < 224) {
                v1 = Bre[(k0 + kk) * 224 + gn];
                v2 = Bim[(k0 + kk) * 224 + gn];
            }
            Bs1[kk][nn] = v1;
            Bs2[kk][nn] = v2;
        }
        __syncthreads();
#pragma unroll
        for (int kk = 0; kk < 8; kk++) {
            unsigned long long a1p[2], a2p[2];
#pragma unroll
            for (int p = 0; p < 2; p++) {
                a1p[p] = *(const unsigned long long*)&As1[kk][ty * 4 + 2 * p];
                a2p[p] = *(const unsigned long long*)&As2[kk][ty * 4 + 2 * p];
            }
            float b1[8], b2[8];
            *(float4*)&b1[0] = *(const float4*)&Bs1[kk][tx * 8];
            *(float4*)&b1[4] = *(const float4*)&Bs1[kk][tx * 8 + 4];
            *(float4*)&b2[0] = *(const float4*)&Bs2[kk][tx * 8];
            *(float4*)&b2[4] = *(const float4*)&Bs2[kk][tx * 8 + 4];
#pragma unroll
            for (int j = 0; j < 8; j++) {
                unsigned long long db1 = dup2(b1[j]);
                unsigned long long db2 = dup2(b2[j]);
                unsigned long long dn2 = dup2(-b2[j]);
#pragma unroll
                for (int p = 0; p < 2; p++) {
                    are2[p][j] = ffma2(a1p[p], db1, are2[p][j]);
                    are2[p][j] = ffma2(a2p[p], dn2, are2[p][j]);
                    aim2[p][j] = ffma2(a1p[p], db2, aim2[p][j]);
                    aim2[p][j] = ffma2(a2p[p], db1, aim2[p][j]);
                }
            }
        }
        __syncthreads();
    }

#pragma unroll
    for (int p = 0; p < 2; p++) {
        long long gm0 = row0 + ty * 4 + 2 * p;
#pragma unroll
        for (int j = 0; j < 8; j++) {
            int gn = col0 + tx * 8 + j;
            if (gn < 224) {
                float2 vr = unpk2(are2[p][j]);
                float2 vi = unpk2(aim2[p][j]);
                Cre[gm0 * 224 + gn] = vr.x;
                Cre[(gm0 + 1) * 224 + gn] = vr.y;
                Cim[gm0 * 224 + gn] = vi.x;
                Cim[(gm0 + 1) * 224 + gn] = vi.y;
            }
        }
    }
}

// ---------------------------------------------------------------------------
// Small kernels
// ---------------------------------------------------------------------------
__global__ void genW_k(float* Wre, float* Wim) {
    int gid = blockIdx.x * blockDim.x + threadIdx.x;
    if (gid >= HW) return;
    int j = gid / IMG, k = gid % IMG;
    int r = (j * k) % IMG;
    float a = 2.f * (float)r / (float)IMG;
    Wre[gid] = cospif(a);
    Wim[gid] = -sinpif(a);
}

__global__ void genD8_k(float* D) {
    int tid = threadIdx.x;
    if (tid >= 64) return;
    int i = tid >> 3, j = tid & 7;
    float v = 0.5f * cospif((float)((2 * j + 1) * i) / 16.f);
    if (i == 0) v *= 0.7071067811865476f;
    D[tid] = v;
}

__global__ void wsum_k(const float* __restrict__ wd1, float* __restrict__ wd1s) {
    int tid = blockIdx.x * blockDim.x + threadIdx.x;
    if (tid >= 288) return;
    int o = tid / 9, r = tid % 9;
    wd1s[tid] = wd1[(o * 3 + 0) * 9 + r] + wd1[(o * 3 + 1) * 9 + r] + wd1[(o * 3 + 2) * 9 + r];
}

__global__ void dct_mean_k(const float* __restrict__ x, const float* __restrict__ D,
                           float* __restrict__ dctimg)
{
    __shared__ float part[8][64];
    __shared__ float Mb[64];
    __shared__ float T[64];
    int b = blockIdx.x;
    int tid = threadIdx.x;
    int ij = tid & 63, ch = tid >> 6;
    int i = ij >> 3, j = ij & 7;
    const float* xb = x + (long long)b * 3 * HW;
    float s = 0.f;
    for (int blk = ch; blk < 784; blk += 8) {
        int m = blk / 28, n = blk % 28;
        int idx = (m * 8 + i) * IMG + (n * 8 + j);
        s += 0.299f * xb[idx] + 0.587f * xb[idx + HW] + 0.114f * xb[idx + 2 * HW];
    }
    part[ch][ij] = s;
    __syncthreads();
    if (tid < 64) {
        float t = 0.f;
        for (int c = 0; c < 8; c++) t += part[c][tid];
        Mb[tid] = t * (255.f / 784.f);
    }
    __syncthreads();
    if (tid < 64) {
        float t = 0.f;
        for (int k = 0; k < 8; k++) t += D[i * 8 + k] * Mb[k * 8 + j];
        T[tid] = t;
    }
    __syncthreads();
    if (tid < 64) {
        float o = 0.f;
        for (int k = 0; k < 8; k++) o += T[i * 8 + k] * D[j * 8 + k];
        dctimg[b * 64 + tid] = o;
    }
}

__global__ void resize_k(const float* __restrict__ dctimg, float* __restrict__ out) {
    int gid = blockIdx.x * blockDim.x + threadIdx.x;
    if (gid >= BATCH * HW) return;
    int ow = gid % IMG;
    int t = gid / IMG;
    int oh = t % IMG;
    int b = t / IMG;
    float fh = (oh + 0.5f) * (8.f / 224.f) - 0.5f;
    float fw = (ow + 0.5f) * (8.f / 224.f) - 0.5f;
    fh = fminf(fmaxf(fh, 0.f), 7.f);
    fw = fminf(fmaxf(fw, 0.f), 7.f);
    int h0 = (int)floorf(fh), w0 = (int)floorf(fw);
    int h1 = min(h0 + 1, 7), w1 = min(w0 + 1, 7);
    float ah = fh - (float)h0, aw = fw - (float)w0;
    const float* d = dctimg + b * 64;
    float v00 = d[h0 * 8 + w0], v01 = d[h0 * 8 + w1];
    float v10 = d[h1 * 8 + w0], v11 = d[h1 * 8 + w1];
    out[gid] = (1.f - ah) * ((1.f - aw) * v00 + aw * v01) + ah * ((1.f - aw) * v10 + aw * v11);
}

__global__ void fftin2_k(const float* __restrict__ Gc, float* __restrict__ fftin,
                         int p, float sgn) {
    __shared__ float tile[32][33];
    int m = blockIdx.z;
    int b = m / 3, c = m % 3;
    int i0 = blockIdx.y * 32;
    int j0 = blockIdx.x * 32;
    int tx = threadIdx.x, ty = threadIdx.y;
    int w = i0 + ty, h = j0 + tx;
    float v;
    if (w < 113) {
        v = Gc[((long long)m * 128 + w) * 224 + h];
    } else {
        int hs = (224 - h) % 224;
        v = sgn * Gc[((long long)m * 128 + (224 - w)) * 224 + hs];
    }
    tile[ty][tx] = v;
    __syncthreads();
    fftin[((long long)(2 * c + p) * BATCH + b) * HW + (j0 + ty) * 224 + (i0 + tx)] = tile[tx][ty];
}

__global__ void pool7_k(const float* __restrict__ src, float* __restrict__ pooled, int base) {
    int gid = blockIdx.x * blockDim.x + threadIdx.x;
    if (gid >= 64 * BATCH * 49) return;
    int j = gid % 7;
    int t = gid / 7;
    int i = t % 7;
    t /= 7;
    int c = t % 64;
    int b = t / 64;
    const float* s = src + ((long long)c * BATCH + b) * 56 * 56;
    float acc = 0.f;
#pragma unroll
    for (int p = 0; p < 8; p++)
#pragma unroll
        for (int q = 0; q < 8; q++)
            acc += s[(i * 8 + p) * 56 + (j * 8 + q)];
    pooled[b * 6272 + base + c * 49 + i * 7 + j] = acc * (1.f / 64.f);
}

__global__ void gap_k(const float* __restrict__ h3, float* __restrict__ comb) {
    int gid = blockIdx.x * blockDim.x + threadIdx.x;
    if (gid >= 512 * BATCH) return;
    int c = gid / BATCH, b = gid % BATCH;
    const float* s = h3 + ((long long)c * BATCH + b) * 196;
    float acc = 0.f;
    for (int t = 0; t < 196; t++) acc += s[t];
    comb[b * 1024 + c] = acc * (1.f / 196.f);
}

__global__ void cls_k(const float* __restrict__ fused, const float* __restrict__ Wc,
                      const float* __restrict__ bc, const float* __restrict__ temp,
                      float* __restrict__ out)
{
    int tid = threadIdx.x;
    if (tid >= 128) return;
    int b = tid >> 1, j = tid & 1;
    float s = bc[j];
    const float* f = fused + b * 512;
    for (int k = 0; k < 512; k++) s += f[k] * Wc[k * 2 + j];
    out[b * 2 + j] = s;
    out[128 + b * 2 + j] = s / temp[0];
}

// ---------------------------------------------------------------------------
static void run_sgemm(const float* A, const float* B, float* C, int M, int N, int K,
                      const float* biasN, int relu,
                      float alpha = 1.f, float beta = 0.f, int ldc = -1, int ldb = -1)
{
    if (ldc < 0) ldc = N;
    if (ldb < 0) ldb = N;
    dim3 grid((N + 127) / 128, (M + 127) / 128);
    sgemm_k<<<grid, 256>>>(A, B, C, M, N, K, ldc, ldb, alpha, beta, biasN, relu);
}

extern "C" void kernel_launch(void* const* d_in, const int* in_sizes, int n_in,
                              void* d_out, int out_size)
{
    const float* x      = (const float*)d_in[0];
    const float* w_stem = (const float*)d_in[1];
    const float* b_stem = (const float*)d_in[2];
    const float* w1     = (const float*)d_in[3];
    const float* b1     = (const float*)d_in[4];
    const float* w2     = (const float*)d_in[5];
    const float* b2     = (const float*)d_in[6];
    const float* w3     = (const float*)d_in[7];
    const float* b3     = (const float*)d_in[8];
    const float* wd1    = (const float*)d_in[9];
    const float* bd1    = (const float*)d_in[10];
    const float* wd2    = (const float*)d_in[11];
    const float* bd2    = (const float*)d_in[12];
    const float* wf1    = (const float*)d_in[13];
    const float* bf1    = (const float*)d_in[14];
    const float* wf2    = (const float*)d_in[15];
    const float* bf2    = (const float*)d_in[16];
    const float* W_freq = (const float*)d_in[17];
    const float* b_freq = (const float*)d_in[18];
    const float* W_fu1  = (const float*)d_in[19];
    const float* b_fu1  = (const float*)d_in[20];
    const float* W_fu2  = (const float*)d_in[21];
    const float* b_fu2  = (const float*)d_in[22];
    const float* W_cls  = (const float*)d_in[23];
    const float* b_cls  = (const float*)d_in[24];
    const float* temp   = (const float*)d_in[25];
    float* out = (float*)d_out;

    float *h0, *h1, *h2, *h3, *hd1, *hd2, *hf1, *hf2;
    float *dctimg, *dctres, *wd1s, *Wre, *Wim, *D8;
    float *Zre, *Zim, *Gre, *Gim, *fftin;
    float *pooled, *comb, *buf1, *fused;
    cudaGetSymbolAddress((void**)&h0, g_h0);
    cudaGetSymbolAddress((void**)&h1, g_h1);
    cudaGetSymbolAddress((void**)&h2, g_h2);
    cudaGetSymbolAddress((void**)&h3, g_h3);
    cudaGetSymbolAddress((void**)&hd1, g_hd1);
    cudaGetSymbolAddress((void**)&hd2, g_hd2);
    cudaGetSymbolAddress((void**)&hf1, g_hf1);
    cudaGetSymbolAddress((void**)&hf2, g_hf2);
    cudaGetSymbolAddress((void**)&dctimg, g_dctimg);
    cudaGetSymbolAddress((void**)&dctres, g_dctres);
    cudaGetSymbolAddress((void**)&wd1s, g_wd1s);
    cudaGetSymbolAddress((void**)&Wre, g_Wre);
    cudaGetSymbolAddress((void**)&Wim, g_Wim);
    cudaGetSymbolAddress((void**)&D8, g_D8);
    cudaGetSymbolAddress((void**)&Zre, g_Zre);
    cudaGetSymbolAddress((void**)&Zim, g_Zim);
    cudaGetSymbolAddress((void**)&Gre, g_Gre);
    cudaGetSymbolAddress((void**)&Gim, g_Gim);
    cudaGetSymbolAddress((void**)&fftin, g_fftin);
    cudaGetSymbolAddress((void**)&pooled, g_pooled);
    cudaGetSymbolAddress((void**)&comb, g_comb);
    cudaGetSymbolAddress((void**)&buf1, g_buf1);
    cudaGetSymbolAddress((void**)&fused, g_fused);

    // ---- init constants ----
    genW_k<<<(HW + 255) / 256, 256>>>(Wre, Wim);
    genD8_k<<<1, 64>>>(D8);
    wsum_k<<<2, 256>>>(wd1, wd1s);

    // ---- CNN backbone (FFMA2 convs, cp.async pipelined) ----
    // stem: 3->64, 7x7 s2 pad2; NC=1 DB=2
    dconv_k<7,7,117,64,1,2><<<dim3(98, 1, BATCH), 128>>>(
        x, w_stem, b_stem, h0, 3, 224, 224, 12544, 2, 2, (long long)HW, 3LL * HW);
    // conv1: 64->128, 112->56; NC=2 DB=2
    dconv_k<3,3,59,128,2,2><<<dim3(25, 1, BATCH), 256>>>(
        h0, w1, b1, h1, 64, 112, 112, 3136, 0, 0, 64LL * 12544, 12544LL);
    // conv2: 128->256, 56->28
    dconv_k<3,3,31,128,2,2><<<dim3(7, 2, BATCH), 256>>>(
        h1, w2, b2, h2, 128, 56, 56, 784, 0, 0, 64LL * 3136, 3136LL);
    // conv3: 256->512, 28->14
    dconv_k<3,3,17,128,2,2><<<dim3(2, 4, BATCH), 256>>>(
        h2, w3, b3, h3, 256, 28, 28, 196, 0, 0, 64LL * 784, 784LL);
    gap_k<<<(512 * BATCH + 255) / 256, 256>>>(h3, comb);

    // ---- DCT branch ----
    dct_mean_k<<<BATCH, 512>>>(x, D8, dctimg);
    resize_k<<<(BATCH * HW + 255) / 256, 256>>>(dctimg, dctres);
    // wd1 (folded, Ci=1): NC=1 DB=1 single shot
    dconv_k<3,3,115,32,1,1><<<dim3(98, 1, BATCH), 64>>>(
        dctres, wd1s, bd1, hd1, 1, 224, 224, 12544, 0, 0, 0LL, (long long)HW);
    // wd2: 32->64; NC=2 DB=2
    dconv_k<3,3,59,64,2,2><<<dim3(25, 1, BATCH), 128>>>(
        hd1, wd2, bd2, hd2, 32, 112, 112, 3136, 0, 0, 64LL * 12544, 12544LL);
    pool7_k<<<(64 * BATCH * 49 + 255) / 256, 256>>>(hd2, pooled, 0);

    // ---- FFT branch (Hermitian-reduced DFT, fp32, no transposes) ----
    dft1_k<<<dim3(1, 672), 256>>>(x, Wre, Wim, Zre, Zim);
    dft2_k<<<dim3(2, 384), 256>>>(Zre, Zim, Wre, Wim, Gre, Gim);
    {
        dim3 tgrid(7, 7, 192), tblk(32, 32);
        fftin2_k<<<tgrid, tblk>>>(Gre, fftin, 0,  1.f);
        fftin2_k<<<tgrid, tblk>>>(Gim, fftin, 1, -1.f);
    }
    // wf1: 6->32; NC=2 DB=2 (3 groups)
    dconv_k<3,3,115,32,2,2><<<dim3(98, 1, BATCH), 64>>>(
        fftin, wf1, bf1, hf1, 6, 224, 224, 12544, 0, 0, (long long)BATCH * HW, (long long)HW);
    // wf2: 32->64; NC=2 DB=2
    dconv_k<3,3,59,64,2,2><<<dim3(25, 1, BATCH), 128>>>(
        hf1, wf2, bf2, hf2, 32, 112, 112, 3136, 0, 0, 64LL * 12544, 12544LL);
    pool7_k<<<(64 * BATCH * 49 + 255) / 256, 256>>>(hf2, pooled, 3136);

    // ---- fusion + classifier (fp32) ----
    run_sgemm(pooled, W_freq, comb + 512, 64, 512, 6272, b_freq, 1, 1.f, 0.f, 1024);
    run_sgemm(comb, W_fu1, buf1, 64, 1024, 1024, b_fu1, 1);
    run_sgemm(buf1, W_fu2, fused, 64, 512, 1024, b_fu2, 1);
    cls_k<<<1, 128>>>(fused, W_cls, b_cls, temp, out);
}

// round 8
// speedup vs baseline: 2.2364x; 1.1518x over previous
#include <cuda_runtime.h>
#include <cuda_bf16.h>
#include <math.h>
#include <stdint.h>

#define BATCH 64
#define IMG 224
#define HW  (IMG*IMG)          // 50176

__device__ float g_h0[64LL*64*112*112];
__device__ float g_h1[128LL*64*56*56];
__device__ float g_h2[256LL*64*28*28];
__device__ float g_h3[512LL*64*14*14];
__device__ float g_hd1[32LL*64*112*112];
__device__ float g_hd2[64LL*64*56*56];
__device__ float g_hf1[32LL*64*112*112];
__device__ float g_hf2[64LL*64*56*56];
__device__ float g_dctimg[BATCH*64];
__device__ float g_dctres[BATCH*HW];
__device__ float g_wd1s[32*9];
__device__ float g_Wre[HW];
__device__ float g_Wim[HW];
__device__ float g_D8[64];
__device__ float g_Zre[43008LL*128];     // [192][224 i][128 kf]
__device__ float g_Zim[43008LL*128];
__device__ float g_Gre[24576LL*224];     // [192][128 kf][224 h]
__device__ float g_Gim[24576LL*224];
__device__ float g_fftin[6LL*BATCH*HW];
__device__ float g_pooled[BATCH*6272];
__device__ float g_comb[BATCH*1024];
__device__ float g_buf1[BATCH*1024];
__device__ float g_fused[BATCH*512];

// ---- packed f32x2 helpers ---------------------------------------------------
__device__ __forceinline__ unsigned long long ffma2(
    unsigned long long a, unsigned long long b, unsigned long long c)
{
    unsigned long long d;
    asm("fma.rn.f32x2 %0, %1, %2, %3;" : "=l"(d) : "l"(a), "l"(b), "l"(c));
    return d;
}
__device__ __forceinline__ unsigned long long dup2(float v) {
    unsigned long long r;
    asm("mov.b64 %0, {%1, %1};" : "=l"(r) : "f"(v));
    return r;
}
__device__ __forceinline__ float2 unpk2(unsigned long long v) {
    float2 f;
    asm("mov.b64 {%0, %1}, %2;" : "=f"(f.x), "=f"(f.y) : "l"(v));
    return f;
}

// ---------------------------------------------------------------------------
// Direct stride-2 conv, parity-split smem staging, FFMA2, cp.async pipeline.
// RM rows/thread (8 or 16); threads NT = 16 * TM / RM.
// Grid: (ceil(OH*OW/128), Co/TM, BATCH).
// ---------------------------------------------------------------------------
template<int KH, int KW, int P, int TM, int NC, int DB, int RM>
__global__ void __launch_bounds__(16*TM/RM) dconv_k(
    const float* __restrict__ src, const float* __restrict__ Wt,
    const float* __restrict__ bias, float* __restrict__ dst,
    int Ci, int H, int W, int OHOW, int padh, int padw,
    long long sC, long long sB)
{
    constexpr int NT = 16 * TM / RM;
    constexpr int PR = RM / 2;
    constexpr int OW = P - (KW / 2) - 2;
    constexpr int NR = 126 / OW + 2;
    constexpr int R  = 2 * (NR - 1) + KH;
    constexpr int KK = KH * KW;
    constexpr int CP = 2 * R * P;
    constexpr int WSZ = KK * TM * NC;
    constexpr int SSZ = CP * NC;

    __shared__ __align__(16) float As[DB * WSZ];
    __shared__ __align__(16) float Sb[DB * SSZ];

    int tid = threadIdx.x;
    int tx = tid & 15, ty = tid >> 4;
    int row0 = blockIdx.y * TM;
    int bz = blockIdx.z;
    int s0 = blockIdx.x * 128;
    int oh_lo = s0 / OW;
    int base_ih = 2 * oh_lo - padh;
    const float* sp = src + bz * sB;

    uint32_t as_u = (uint32_t)__cvta_generic_to_shared(As);
    uint32_t sb_u = (uint32_t)__cvta_generic_to_shared(Sb);

    int pbase[8];
    unsigned okmask = 0;
#pragma unroll
    for (int j = 0; j < 8; j++) {
        int s = s0 + j * 16 + tx;
        if (s < OHOW) okmask |= (1u << j);
        int sc = (s < OHOW) ? s : (OHOW - 1);
        int oh = sc / OW;
        int ow = sc - oh * OW;
        pbase[j] = 2 * (oh - oh_lo) * P + ow;
    }

    unsigned long long acc2[PR][8];
#pragma unroll
    for (int p = 0; p < PR; p++)
#pragma unroll
        for (int j = 0; j < 8; j++) acc2[p][j] = 0ULL;

    auto stage = [&](int c0, int pp) {
        uint32_t ab = as_u + pp * WSZ * 4;
        for (int t = tid; t < WSZ; t += NT) {
            int cc = t / (KK * TM);
            int rem = t - cc * (KK * TM);
            int m = rem / KK, tap = rem - m * KK;
            const float* g = Wt + (long long)(row0 + m) * (Ci * KK) + (c0 + cc) * KK + tap;
            uint32_t d = ab + (uint32_t)(((cc * KK + tap) * TM + m) * 4);
            asm volatile("cp.async.ca.shared.global [%0], [%1], 4;" :: "r"(d), "l"(g));
        }
        uint32_t sbb = sb_u + pp * SSZ * 4;
        for (int t = tid; t < SSZ; t += NT) {
            int cc = t / CP;
            int rem = t - cc * CP;
            int r = rem / (2 * P);
            int u = rem - r * 2 * P;
            int ih = base_ih + r;
            int ic = u - padw;
            bool ok = ((unsigned)ih < (unsigned)H) && ((unsigned)ic < (unsigned)W);
            const float* g = sp + (c0 + cc) * sC + (ok ? ((long long)ih * W + ic) : 0LL);
            uint32_t d = sbb + (uint32_t)((cc * CP + (u & 1) * (R * P) + r * P + (u >> 1)) * 4);
            int sz = ok ? 4 : 0;
            asm volatile("cp.async.ca.shared.global [%0], [%1], 4, %2;"
                         :: "r"(d), "l"(g), "r"(sz));
        }
        asm volatile("cp.async.commit_group;");
    };

    auto compute = [&](int pp) {
        const float* Ap = As + pp * WSZ;
        const float* Bp = Sb + pp * SSZ;
#pragma unroll
        for (int cc = 0; cc < NC; cc++) {
#pragma unroll
            for (int kh = 0; kh < KH; kh++) {
#pragma unroll
                for (int kw = 0; kw < KW; kw++) {
                    const ulonglong2* awv = (const ulonglong2*)
                        (Ap + (cc * KK + kh * KW + kw) * TM + ty * RM);
                    const float* bb = Bp + cc * CP + (kw & 1) * (R * P) + kh * P + (kw >> 1);
                    unsigned long long a2[PR];
#pragma unroll
                    for (int v = 0; v < PR / 2; v++) {
                        ulonglong2 t = awv[v];
                        a2[2 * v] = t.x;
                        a2[2 * v + 1] = t.y;
                    }
#pragma unroll
                    for (int j = 0; j < 8; j++) {
                        unsigned long long b2 = dup2(bb[pbase[j]]);
#pragma unroll
                        for (int p = 0; p < PR; p++)
                            acc2[p][j] = ffma2(a2[p], b2, acc2[p][j]);
                    }
                }
            }
        }
    };

    stage(0, 0);
    int p = 0;
    for (int c0 = 0; c0 < Ci; c0 += NC) {
        if (DB == 2) {
            if (c0 + NC < Ci) {
                stage(c0 + NC, p ^ 1);
                asm volatile("cp.async.wait_group 1;");
            } else {
                asm volatile("cp.async.wait_group 0;");
            }
        } else {
            asm volatile("cp.async.wait_group 0;");
        }
        __syncthreads();
        compute(p);
        __syncthreads();
        p ^= 1;
    }

    long long NtotG = (long long)BATCH * OHOW;
#pragma unroll
    for (int q = 0; q < PR; q++) {
        int gm0 = row0 + ty * RM + 2 * q;
        float bm0 = bias[gm0], bm1 = bias[gm0 + 1];
        float* d0 = dst + (long long)gm0 * NtotG + (long long)bz * OHOW;
        float* d1 = d0 + NtotG;
#pragma unroll
        for (int j = 0; j < 8; j++) {
            if (okmask & (1u << j)) {
                int s = s0 + j * 16 + tx;
                float2 v = unpk2(acc2[q][j]);
                d0[s] = fmaxf(v.x + bm0, 0.f);
                d1[s] = fmaxf(v.y + bm1, 0.f);
            }
        }
    }
}

// ---------------------------------------------------------------------------
// Dense SGEMM, FFMA2 (FC layers)
// ---------------------------------------------------------------------------
__global__ void __launch_bounds__(256) sgemm_k(
    const float* __restrict__ A, const float* __restrict__ B, float* __restrict__ C,
    int M, int N, int K, int ldc, int ldb, float alpha, float beta,
    const float* __restrict__ biasN, int relu)
{
    __shared__ __align__(16) float As[8][128];
    __shared__ __align__(16) float Bs[8][128];
    int tid = threadIdx.x;
    int tx = tid & 15, ty = tid >> 4;
    int row0 = blockIdx.y * 128, col0 = blockIdx.x * 128;

    unsigned long long acc2[4][8];
#pragma unroll
    for (int p = 0; p < 4; p++)
#pragma unroll
        for (int j = 0; j < 8; j++) acc2[p][j] = 0ULL;

    for (int k0 = 0; k0 < K; k0 += 8) {
#pragma unroll
        for (int i = 0; i < 4; i++) {
            int idx = tid + i * 256;
            int m = idx >> 3, kk = idx & 7;
            int gm = row0 + m, gk = k0 + kk;
            float v = 0.f;
            if (gm < M && gk < K) v = A[(long long)gm * K + gk];
            As[kk][m] = v;
        }
#pragma unroll
        for (int i = 0; i < 4; i++) {
            int idx = tid + i * 256;
            int kk = idx >> 7, nn = idx & 127;
            int gn = col0 + nn, gk = k0 + kk;
            float v = 0.f;
            if (gk < K && gn < N) v = B[(long long)gk * ldb + gn];
            Bs[kk][nn] = v;
        }
        __syncthreads();
#pragma unroll
        for (int kk = 0; kk < 8; kk++) {
            unsigned long long a2[4];
#pragma unroll
            for (int p = 0; p < 4; p++)
                a2[p] = *(const unsigned long long*)&As[kk][ty * 8 + 2 * p];
            float b[8];
            *(float4*)&b[0] = *(const float4*)&Bs[kk][tx * 8];
            *(float4*)&b[4] = *(const float4*)&Bs[kk][tx * 8 + 4];
#pragma unroll
            for (int j = 0; j < 8; j++) {
                unsigned long long b2 = dup2(b[j]);
#pragma unroll
                for (int p = 0; p < 4; p++)
                    acc2[p][j] = ffma2(a2[p], b2, acc2[p][j]);
            }
        }
        __syncthreads();
    }

#pragma unroll
    for (int p = 0; p < 4; p++) {
        int gm0 = row0 + ty * 8 + 2 * p;
#pragma unroll
        for (int j = 0; j < 8; j++) {
            int gn = col0 + tx * 8 + j;
            if (gn >= N) continue;
            float2 v2 = unpk2(acc2[p][j]);
            float vv[2] = {v2.x, v2.y};
#pragma unroll
            for (int q = 0; q < 2; q++) {
                int gm = gm0 + q;
                if (gm >= M) continue;
                float v = alpha * vv[q];
                if (beta != 0.f) v += beta * C[(long long)gm * ldc + gn];
                if (biasN) v += biasN[gn];
                if (relu) v = fmaxf(v, 0.f);
                C[(long long)gm * ldc + gn] = v;
            }
        }
    }
}

// ---------------------------------------------------------------------------
// Split-K FC GEMM: C[64,N] += A[64,K-chunk] * B[K-chunk,N] via atomicAdd.
// grid: (N/128, KSPLIT), block 256. C must be pre-zeroed.
// ---------------------------------------------------------------------------
__global__ void __launch_bounds__(256) fcsplit_k(
    const float* __restrict__ A, const float* __restrict__ B, float* __restrict__ C,
    int K, int N)
{
    __shared__ __align__(16) float As[8][64];
    __shared__ __align__(16) float Bs[8][128];
    int tid = threadIdx.x;
    int tx = tid & 15, ty = tid >> 4;
    int col0 = blockIdx.x * 128;
    int kc = K / gridDim.y;
    int kb = blockIdx.y * kc;

    float acc[4][8];
#pragma unroll
    for (int i = 0; i < 4; i++)
#pragma unroll
        for (int j = 0; j < 8; j++) acc[i][j] = 0.f;

    for (int k0 = kb; k0 < kb + kc; k0 += 8) {
#pragma unroll
        for (int i = 0; i < 2; i++) {
            int idx = tid + i * 256;
            int m = idx >> 3, kk = idx & 7;
            As[kk][m] = A[(long long)m * K + k0 + kk];
        }
#pragma unroll
        for (int i = 0; i < 4; i++) {
            int idx = tid + i * 256;
            int kk = idx >> 7, nn = idx & 127;
            int gn = col0 + nn;
            Bs[kk][nn] = (gn < N) ? B[(long long)(k0 + kk) * N + gn] : 0.f;
        }
        __syncthreads();
#pragma unroll
        for (int kk = 0; kk < 8; kk++) {
            float a[4], b[8];
            *(float4*)&a[0] = *(const float4*)&As[kk][ty * 4];
            *(float4*)&b[0] = *(const float4*)&Bs[kk][tx * 8];
            *(float4*)&b[4] = *(const float4*)&Bs[kk][tx * 8 + 4];
#pragma unroll
            for (int i = 0; i < 4; i++)
#pragma unroll
                for (int j = 0; j < 8; j++) acc[i][j] += a[i] * b[j];
        }
        __syncthreads();
    }

#pragma unroll
    for (int i = 0; i < 4; i++) {
        int gm = ty * 4 + i;
#pragma unroll
        for (int j = 0; j < 8; j++) {
            int gn = col0 + tx * 8 + j;
            if (gn < N) atomicAdd(&C[(long long)gm * N + gn], acc[i][j]);
        }
    }
}

__global__ void fcfin_k(const float* __restrict__ buf, const float* __restrict__ bias,
                        float* __restrict__ comb)
{
    int gid = blockIdx.x * blockDim.x + threadIdx.x;
    if (gid >= 64 * 512) return;
    int b = gid >> 9, c = gid & 511;
    comb[b * 1024 + 512 + c] = fmaxf(buf[gid] + bias[c], 0.f);
}

// ---------------------------------------------------------------------------
// DFT stage 1 fused: Zre/Zim = X * W[:, :128]; Z layout [img][i][kf].
// ---------------------------------------------------------------------------
__global__ void __launch_bounds__(256) dft1_k(
    const float* __restrict__ X,
    const float* __restrict__ Bre, const float* __restrict__ Bim,
    float* __restrict__ Zre, float* __restrict__ Zim)
{
    __shared__ __align__(16) float As[8][64];
    __shared__ __align__(16) float Bs1[8][128], Bs2[8][128];
    int tid = threadIdx.x;
    int tx = tid & 15, ty = tid >> 4;
    int row0 = blockIdx.y * 64;

    unsigned long long zre[2][8], zim[2][8];
#pragma unroll
    for (int p = 0; p < 2; p++)
#pragma unroll
        for (int j = 0; j < 8; j++) { zre[p][j] = 0ULL; zim[p][j] = 0ULL; }

    for (int k0 = 0; k0 < 224; k0 += 8) {
#pragma unroll
        for (int i = 0; i < 2; i++) {
            int idx = tid + i * 256;
            int m = idx >> 3, kk = idx & 7;
            As[kk][m] = X[(long long)(row0 + m) * 224 + k0 + kk];
        }
#pragma unroll
        for (int i = 0; i < 4; i++) {
            int idx = tid + i * 256;
            int kk = idx >> 7, nn = idx & 127;
            Bs1[kk][nn] = Bre[(k0 + kk) * 224 + nn];
            Bs2[kk][nn] = Bim[(k0 + kk) * 224 + nn];
        }
        __syncthreads();
#pragma unroll
        for (int kk = 0; kk < 8; kk++) {
            unsigned long long a2[2];
#pragma unroll
            for (int p = 0; p < 2; p++)
                a2[p] = *(const unsigned long long*)&As[kk][ty * 4 + 2 * p];
            float b1[8], b2[8];
            *(float4*)&b1[0] = *(const float4*)&Bs1[kk][tx * 8];
            *(float4*)&b1[4] = *(const float4*)&Bs1[kk][tx * 8 + 4];
            *(float4*)&b2[0] = *(const float4*)&Bs2[kk][tx * 8];
            *(float4*)&b2[4] = *(const float4*)&Bs2[kk][tx * 8 + 4];
#pragma unroll
            for (int j = 0; j < 8; j++) {
                unsigned long long db1 = dup2(b1[j]);
                unsigned long long db2 = dup2(b2[j]);
#pragma unroll
                for (int p = 0; p < 2; p++) {
                    zre[p][j] = ffma2(a2[p], db1, zre[p][j]);
                    zim[p][j] = ffma2(a2[p], db2, zim[p][j]);
                }
            }
        }
        __syncthreads();
    }

#pragma unroll
    for (int p = 0; p < 2; p++) {
        long long gm0 = row0 + ty * 4 + 2 * p;
#pragma unroll
        for (int j = 0; j < 8; j++) {
            int gn = tx * 8 + j;
            float2 vr = unpk2(zre[p][j]);
            float2 vi = unpk2(zim[p][j]);
            Zre[gm0 * 128 + gn] = vr.x;
            Zre[(gm0 + 1) * 128 + gn] = vr.y;
            Zim[gm0 * 128 + gn] = vi.x;
            Zim[(gm0 + 1) * 128 + gn] = vi.y;
        }
    }
}

// ---------------------------------------------------------------------------
// DFT stage 2 fused complex GEMM (reads Z [img][i][kf] directly).
// ---------------------------------------------------------------------------
__global__ void __launch_bounds__(256) dft2_k(
    const float* __restrict__ Zre, const float* __restrict__ Zim,
    const float* __restrict__ Bre, const float* __restrict__ Bim,
    float* __restrict__ Cre, float* __restrict__ Cim)
{
    __shared__ __align__(16) float As1[8][64], As2[8][64];
    __shared__ __align__(16) float Bs1[8][128], Bs2[8][128];
    int tid = threadIdx.x;
    int tx = tid & 15, ty = tid >> 4;
    int row0 = blockIdx.y * 64, col0 = blockIdx.x * 128;
    int img = row0 >> 7;
    int kf0 = row0 & 127;

    unsigned long long are2[2][8], aim2[2][8];
#pragma unroll
    for (int p = 0; p < 2; p++)
#pragma unroll
        for (int j = 0; j < 8; j++) { are2[p][j] = 0ULL; aim2[p][j] = 0ULL; }

    for (int k0 = 0; k0 < 224; k0 += 8) {
#pragma unroll
        for (int i = 0; i < 2; i++) {
            int idx = tid + i * 256;
            int m = idx >> 3, kk = idx & 7;
            long long zoff = ((long long)img * 224 + k0 + kk) * 128 + kf0 + m;
            As1[kk][m] = Zre[zoff];
            As2[kk][m] = Zim[zoff];
        }
#pragma unroll
        for (int i = 0; i < 4; i++) {
            int idx = tid + i * 256;
            int kk = idx >> 7, nn = idx & 127;
            int gn = col0 + nn;
            float v1 = 0.f, v2 = 0.f;
            if (gn < 224) {
                v1 = Bre[(k0 + kk) * 224 + gn];
                v2 = Bim[(k0 + kk) * 224 + gn];
            }
            Bs1[kk][nn] = v1;
            Bs2[kk][nn] = v2;
        }
        __syncthreads();
#pragma unroll
        for (int kk = 0; kk < 8; kk++) {
            unsigned long long a1p[2], a2p[2];
#pragma unroll
            for (int p = 0; p < 2; p++) {
                a1p[p] = *(const unsigned long long*)&As1[kk][ty * 4 + 2 * p];
                a2p[p] = *(const unsigned long long*)&As2[kk][ty * 4 + 2 * p];
            }
            float b1[8], b2[8];
            *(float4*)&b1[0] = *(const float4*)&Bs1[kk][tx * 8];
            *(float4*)&b1[4] = *(const float4*)&Bs1[kk][tx * 8 + 4];
            *(float4*)&b2[0] = *(const float4*)&Bs2[kk][tx * 8];
            *(float4*)&b2[4] = *(const float4*)&Bs2[kk][tx * 8 + 4];
#pragma unroll
            for (int j = 0; j < 8; j++) {
                unsigned long long db1 = dup2(b1[j]);
                unsigned long long db2 = dup2(b2[j]);
                unsigned long long dn2 = dup2(-b2[j]);
#pragma unroll
                for (int p = 0; p < 2; p++) {
                    are2[p][j] = ffma2(a1p[p], db1, are2[p][j]);
                    are2[p][j] = ffma2(a2p[p], dn2, are2[p][j]);
                    aim2[p][j] = ffma2(a1p[p], db2, aim2[p][j]);
                    aim2[p][j] = ffma2(a2p[p], db1, aim2[p][j]);
                }
            }
        }
        __syncthreads();
    }

#pragma unroll
    for (int p = 0; p < 2; p++) {
        long long gm0 = row0 + ty * 4 + 2 * p;
#pragma unroll
        for (int j = 0; j < 8; j++) {
            int gn = col0 + tx * 8 + j;
            if (gn < 224) {
                float2 vr = unpk2(are2[p][j]);
                float2 vi = unpk2(aim2[p][j]);
                Cre[gm0 * 224 + gn] = vr.x;
                Cre[(gm0 + 1) * 224 + gn] = vr.y;
                Cim[gm0 * 224 + gn] = vi.x;
                Cim[(gm0 + 1) * 224 + gn] = vi.y;
            }
        }
    }
}

// ---------------------------------------------------------------------------
// Small kernels
// ---------------------------------------------------------------------------
__global__ void genW_k(float* Wre, float* Wim) {
    int gid = blockIdx.x * blockDim.x + threadIdx.x;
    if (gid >= HW) return;
    int j = gid / IMG, k = gid % IMG;
    int r = (j * k) % IMG;
    float a = 2.f * (float)r / (float)IMG;
    Wre[gid] = cospif(a);
    Wim[gid] = -sinpif(a);
}

__global__ void genD8_k(float* D) {
    int tid = threadIdx.x;
    if (tid >= 64) return;
    int i = tid >> 3, j = tid & 7;
    float v = 0.5f * cospif((float)((2 * j + 1) * i) / 16.f);
    if (i == 0) v *= 0.7071067811865476f;
    D[tid] = v;
}

__global__ void wsum_k(const float* __restrict__ wd1, float* __restrict__ wd1s) {
    int tid = blockIdx.x * blockDim.x + threadIdx.x;
    if (tid >= 288) return;
    int o = tid / 9, r = tid % 9;
    wd1s[tid] = wd1[(o * 3 + 0) * 9 + r] + wd1[(o * 3 + 1) * 9 + r] + wd1[(o * 3 + 2) * 9 + r];
}

__global__ void dct_mean_k(const float* __restrict__ x, const float* __restrict__ D,
                           float* __restrict__ dctimg)
{
    __shared__ float part[8][64];
    __shared__ float Mb[64];
    __shared__ float T[64];
    int b = blockIdx.x;
    int tid = threadIdx.x;
    int ij = tid & 63, ch = tid >> 6;
    int i = ij >> 3, j = ij & 7;
    const float* xb = x + (long long)b * 3 * HW;
    float s = 0.f;
    for (int blk = ch; blk < 784; blk += 8) {
        int m = blk / 28, n = blk % 28;
        int idx = (m * 8 + i) * IMG + (n * 8 + j);
        s += 0.299f * xb[idx] + 0.587f * xb[idx + HW] + 0.114f * xb[idx + 2 * HW];
    }
    part[ch][ij] = s;
    __syncthreads();
    if (tid < 64) {
        float t = 0.f;
        for (int c = 0; c < 8; c++) t += part[c][tid];
        Mb[tid] = t * (255.f / 784.f);
    }
    __syncthreads();
    if (tid < 64) {
        float t = 0.f;
        for (int k = 0; k < 8; k++) t += D[i * 8 + k] * Mb[k * 8 + j];
        T[tid] = t;
    }
    __syncthreads();
    if (tid < 64) {
        float o = 0.f;
        for (int k = 0; k < 8; k++) o += T[i * 8 + k] * D[j * 8 + k];
        dctimg[b * 64 + tid] = o;
    }
}

__global__ void resize_k(const float* __restrict__ dctimg, float* __restrict__ out) {
    int gid = blockIdx.x * blockDim.x + threadIdx.x;
    if (gid >= BATCH * HW) return;
    int ow = gid % IMG;
    int t = gid / IMG;
    int oh = t % IMG;
    int b = t / IMG;
    float fh = (oh + 0.5f) * (8.f / 224.f) - 0.5f;
    float fw = (ow + 0.5f) * (8.f / 224.f) - 0.5f;
    fh = fminf(fmaxf(fh, 0.f), 7.f);
    fw = fminf(fmaxf(fw, 0.f), 7.f);
    int h0 = (int)floorf(fh), w0 = (int)floorf(fw);
    int h1 = min(h0 + 1, 7), w1 = min(w0 + 1, 7);
    float ah = fh - (float)h0, aw = fw - (float)w0;
    const float* d = dctimg + b * 64;
    float v00 = d[h0 * 8 + w0], v01 = d[h0 * 8 + w1];
    float v10 = d[h1 * 8 + w0], v11 = d[h1 * 8 + w1];
    out[gid] = (1.f - ah) * ((1.f - aw) * v00 + aw * v01) + ah * ((1.f - aw) * v10 + aw * v11);
}

__global__ void fftin2_k(const float* __restrict__ Gc, float* __restrict__ fftin,
                         int p, float sgn) {
    __shared__ float tile[32][33];
    int m = blockIdx.z;
    int b = m / 3, c = m % 3;
    int i0 = blockIdx.y * 32;
    int j0 = blockIdx.x * 32;
    int tx = threadIdx.x, ty = threadIdx.y;
    int w = i0 + ty, h = j0 + tx;
    float v;
    if (w < 113) {
        v = Gc[((long long)m * 128 + w) * 224 + h];
    } else {
        int hs = (224 - h) % 224;
        v = sgn * Gc[((long long)m * 128 + (224 - w)) * 224 + hs];
    }
    tile[ty][tx] = v;
    __syncthreads();
    fftin[((long long)(2 * c + p) * BATCH + b) * HW + (j0 + ty) * 224 + (i0 + tx)] = tile[tx][ty];
}

__global__ void pool7_k(const float* __restrict__ src, float* __restrict__ pooled, int base) {
    int gid = blockIdx.x * blockDim.x + threadIdx.x;
    if (gid >= 64 * BATCH * 49) return;
    int j = gid % 7;
    int t = gid / 7;
    int i = t % 7;
    t /= 7;
    int c = t % 64;
    int b = t / 64;
    const float* s = src + ((long long)c * BATCH + b) * 56 * 56;
    float acc = 0.f;
#pragma unroll
    for (int p = 0; p < 8; p++)
#pragma unroll
        for (int q = 0; q < 8; q++)
            acc += s[(i * 8 + p) * 56 + (j * 8 + q)];
    pooled[b * 6272 + base + c * 49 + i * 7 + j] = acc * (1.f / 64.f);
}

__global__ void gap_k(const float* __restrict__ h3, float* __restrict__ comb) {
    int gid = blockIdx.x * blockDim.x + threadIdx.x;
    if (gid >= 512 * BATCH) return;
    int c = gid / BATCH, b = gid % BATCH;
    const float* s = h3 + ((long long)c * BATCH + b) * 196;
    float acc = 0.f;
    for (int t = 0; t < 196; t++) acc += s[t];
    comb[b * 1024 + c] = acc * (1.f / 196.f);
}

__global__ void cls_k(const float* __restrict__ fused, const float* __restrict__ Wc,
                      const float* __restrict__ bc, const float* __restrict__ temp,
                      float* __restrict__ out)
{
    int tid = threadIdx.x;
    if (tid >= 128) return;
    int b = tid >> 1, j = tid & 1;
    float s = bc[j];
    const float* f = fused + b * 512;
    for (int k = 0; k < 512; k++) s += f[k] * Wc[k * 2 + j];
    out[b * 2 + j] = s;
    out[128 + b * 2 + j] = s / temp[0];
}

// ---------------------------------------------------------------------------
static void run_sgemm(const float* A, const float* B, float* C, int M, int N, int K,
                      const float* biasN, int relu,
                      float alpha = 1.f, float beta = 0.f, int ldc = -1, int ldb = -1)
{
    if (ldc < 0) ldc = N;
    if (ldb < 0) ldb = N;
    dim3 grid((N + 127) / 128, (M + 127) / 128);
    sgemm_k<<<grid, 256>>>(A, B, C, M, N, K, ldc, ldb, alpha, beta, biasN, relu);
}

extern "C" void kernel_launch(void* const* d_in, const int* in_sizes, int n_in,
                              void* d_out, int out_size)
{
    const float* x      = (const float*)d_in[0];
    const float* w_stem = (const float*)d_in[1];
    const float* b_stem = (const float*)d_in[2];
    const float* w1     = (const float*)d_in[3];
    const float* b1     = (const float*)d_in[4];
    const float* w2     = (const float*)d_in[5];
    const float* b2     = (const float*)d_in[6];
    const float* w3     = (const float*)d_in[7];
    const float* b3     = (const float*)d_in[8];
    const float* wd1    = (const float*)d_in[9];
    const float* bd1    = (const float*)d_in[10];
    const float* wd2    = (const float*)d_in[11];
    const float* bd2    = (const float*)d_in[12];
    const float* wf1    = (const float*)d_in[13];
    const float* bf1    = (const float*)d_in[14];
    const float* wf2    = (const float*)d_in[15];
    const float* bf2    = (const float*)d_in[16];
    const float* W_freq = (const float*)d_in[17];
    const float* b_freq = (const float*)d_in[18];
    const float* W_fu1  = (const float*)d_in[19];
    const float* b_fu1  = (const float*)d_in[20];
    const float* W_fu2  = (const float*)d_in[21];
    const float* b_fu2  = (const float*)d_in[22];
    const float* W_cls  = (const float*)d_in[23];
    const float* b_cls  = (const float*)d_in[24];
    const float* temp   = (const float*)d_in[25];
    float* out = (float*)d_out;

    float *h0, *h1, *h2, *h3, *hd1, *hd2, *hf1, *hf2;
    float *dctimg, *dctres, *wd1s, *Wre, *Wim, *D8;
    float *Zre, *Zim, *Gre, *Gim, *fftin;
    float *pooled, *comb, *buf1, *fused;
    cudaGetSymbolAddress((void**)&h0, g_h0);
    cudaGetSymbolAddress((void**)&h1, g_h1);
    cudaGetSymbolAddress((void**)&h2, g_h2);
    cudaGetSymbolAddress((void**)&h3, g_h3);
    cudaGetSymbolAddress((void**)&hd1, g_hd1);
    cudaGetSymbolAddress((void**)&hd2, g_hd2);
    cudaGetSymbolAddress((void**)&hf1, g_hf1);
    cudaGetSymbolAddress((void**)&hf2, g_hf2);
    cudaGetSymbolAddress((void**)&dctimg, g_dctimg);
    cudaGetSymbolAddress((void**)&dctres, g_dctres);
    cudaGetSymbolAddress((void**)&wd1s, g_wd1s);
    cudaGetSymbolAddress((void**)&Wre, g_Wre);
    cudaGetSymbolAddress((void**)&Wim, g_Wim);
    cudaGetSymbolAddress((void**)&D8, g_D8);
    cudaGetSymbolAddress((void**)&Zre, g_Zre);
    cudaGetSymbolAddress((void**)&Zim, g_Zim);
    cudaGetSymbolAddress((void**)&Gre, g_Gre);
    cudaGetSymbolAddress((void**)&Gim, g_Gim);
    cudaGetSymbolAddress((void**)&fftin, g_fftin);
    cudaGetSymbolAddress((void**)&pooled, g_pooled);
    cudaGetSymbolAddress((void**)&comb, g_comb);
    cudaGetSymbolAddress((void**)&buf1, g_buf1);
    cudaGetSymbolAddress((void**)&fused, g_fused);

    // ---- init constants ----
    genW_k<<<(HW + 255) / 256, 256>>>(Wre, Wim);
    genD8_k<<<1, 64>>>(D8);
    wsum_k<<<2, 256>>>(wd1, wd1s);

    // ---- CNN backbone (FFMA2 convs, RM=16) ----
    dconv_k<7,7,117,64,1,2,16><<<dim3(98, 1, BATCH), 64>>>(
        x, w_stem, b_stem, h0, 3, 224, 224, 12544, 2, 2, (long long)HW, 3LL * HW);
    dconv_k<3,3,59,128,2,2,16><<<dim3(25, 1, BATCH), 128>>>(
        h0, w1, b1, h1, 64, 112, 112, 3136, 0, 0, 64LL * 12544, 12544LL);
    dconv_k<3,3,31,128,2,2,16><<<dim3(7, 2, BATCH), 128>>>(
        h1, w2, b2, h2, 128, 56, 56, 784, 0, 0, 64LL * 3136, 3136LL);
    dconv_k<3,3,17,128,2,2,16><<<dim3(2, 4, BATCH), 128>>>(
        h2, w3, b3, h3, 256, 28, 28, 196, 0, 0, 64LL * 784, 784LL);
    gap_k<<<(512 * BATCH + 255) / 256, 256>>>(h3, comb);

    // ---- DCT branch ----
    dct_mean_k<<<BATCH, 512>>>(x, D8, dctimg);
    resize_k<<<(BATCH * HW + 255) / 256, 256>>>(dctimg, dctres);
    dconv_k<3,3,115,32,1,1,8><<<dim3(98, 1, BATCH), 64>>>(
        dctres, wd1s, bd1, hd1, 1, 224, 224, 12544, 0, 0, 0LL, (long long)HW);
    dconv_k<3,3,59,64,2,2,16><<<dim3(25, 1, BATCH), 64>>>(
        hd1, wd2, bd2, hd2, 32, 112, 112, 3136, 0, 0, 64LL * 12544, 12544LL);
    pool7_k<<<(64 * BATCH * 49 + 255) / 256, 256>>>(hd2, pooled, 0);

    // ---- FFT branch ----
    dft1_k<<<dim3(1, 672), 256>>>(x, Wre, Wim, Zre, Zim);
    dft2_k<<<dim3(2, 384), 256>>>(Zre, Zim, Wre, Wim, Gre, Gim);
    {
        dim3 tgrid(7, 7, 192), tblk(32, 32);
        fftin2_k<<<tgrid, tblk>>>(Gre, fftin, 0,  1.f);
        fftin2_k<<<tgrid, tblk>>>(Gim, fftin, 1, -1.f);
    }
    dconv_k<3,3,115,32,2,2,8><<<dim3(98, 1, BATCH), 64>>>(
        fftin, wf1, bf1, hf1, 6, 224, 224, 12544, 0, 0, (long long)BATCH * HW, (long long)HW);
    dconv_k<3,3,59,64,2,2,16><<<dim3(25, 1, BATCH), 64>>>(
        hf1, wf2, bf2, hf2, 32, 112, 112, 3136, 0, 0, 64LL * 12544, 12544LL);
    pool7_k<<<(64 * BATCH * 49 + 255) / 256, 256>>>(hf2, pooled, 3136);

    // ---- fusion + classifier ----
    cudaMemsetAsync(buf1, 0, 64 * 512 * sizeof(float));
    fcsplit_k<<<dim3(4, 8), 256>>>(pooled, W_freq, buf1, 6272, 512);
    fcfin_k<<<(64 * 512 + 255) / 256, 256>>>(buf1, b_freq, comb);
    run_sgemm(comb, W_fu1, buf1, 64, 1024, 1024, b_fu1, 1);
    run_sgemm(buf1, W_fu2, fused, 64, 512, 1024, b_fu2, 1);
    cls_k<<<1, 128>>>(fused, W_cls, b_cls, temp, out);
}